// round 13
// baseline (speedup 1.0000x reference)
#include <cuda_runtime.h>
#include <cuda_bf16.h>
#include <math.h>
#include <stdint.h>

#define BB 2
#define NTOK 8192
#define DIMX 512
#define NH 8
#define DH 64
#define ML 256
#define BHN 16

__device__ float g_q [BHN*NTOK*DH];
__device__ float g_k [BHN*NTOK*DH];
__device__ float g_v [BHN*NTOK*DH];
__device__ float g_ql[BHN*ML*DH];
__device__ float g_kl[BHN*ML*DH];
__device__ float g_a2[BHN*ML*ML];
__device__ float g_z0[BHN*ML*ML];
__device__ float g_z1[BHN*ML*ML];
__device__ float g_xz[BHN*ML*ML];
__device__ float g_t1[BHN*ML*ML];
__device__ float g_t2[BHN*ML*ML];
__device__ float g_sim3[(size_t)BHN*ML*NTOK];
__device__ float g_a3vp[8*BHN*ML*DH];
__device__ float g_a3v [BHN*ML*DH];
__device__ float g_Z2  [BHN*ML*DH];
__device__ float g_attn[BB*NTOK*DIMX];
__device__ float g_scal[2];
__device__ __nv_bfloat16 g_bhi[BB*NTOK*DIMX];
__device__ __nv_bfloat16 g_blo[BB*NTOK*DIMX];
__device__ __nv_bfloat16 g_wqhi[1536*512];
__device__ __nv_bfloat16 g_wqlo[1536*512];
__device__ __nv_bfloat16 g_wohi[512*512];
__device__ __nv_bfloat16 g_wolo[512*512];
// bf16 operands for attention GEMMs
__device__ __nv_bfloat16 g_qhi[BHN*NTOK*DH], g_qlo[BHN*NTOK*DH];
__device__ __nv_bfloat16 g_khi[BHN*NTOK*DH], g_klo[BHN*NTOK*DH];
__device__ __nv_bfloat16 g_qlhi[BHN*ML*DH], g_qllo[BHN*ML*DH];
__device__ __nv_bfloat16 g_klhi[BHN*ML*DH], g_kllo[BHN*ML*DH];
__device__ __nv_bfloat16 g_vthi[BHN*DH*NTOK], g_vtlo[BHN*DH*NTOK];
__device__ __nv_bfloat16 g_z2thi[BHN*DH*ML], g_z2tlo[BHN*DH*ML];
__device__ __nv_bfloat16 g_a3hi[(size_t)BHN*ML*NTOK], g_a3lo[(size_t)BHN*ML*NTOK];

// ================= bf16 mma.sync + ldmatrix =================
__device__ __forceinline__ void mma16816(float* c, const uint32_t* a, const uint32_t* b){
    asm volatile("mma.sync.aligned.m16n8k16.row.col.f32.bf16.bf16.f32 "
        "{%0,%1,%2,%3},{%4,%5,%6,%7},{%8,%9},{%0,%1,%2,%3};"
        : "+f"(c[0]),"+f"(c[1]),"+f"(c[2]),"+f"(c[3])
        : "r"(a[0]),"r"(a[1]),"r"(a[2]),"r"(a[3]),"r"(b[0]),"r"(b[1]));
}
__device__ __forceinline__ uint32_t cvta_s(const void* p){
    uint32_t a;
    asm("{ .reg .u64 t; cvta.to.shared.u64 t, %1; cvt.u32.u64 %0, t; }" : "=r"(a) : "l"(p));
    return a;
}
#define LDSM4(r, a) \
    asm volatile("ldmatrix.sync.aligned.m8n8.x4.shared.b16 {%0,%1,%2,%3}, [%4];" \
        : "=r"((r)[0]),"=r"((r)[1]),"=r"((r)[2]),"=r"((r)[3]) : "r"(a))
#define SWZ(o) ((o) ^ (((o)>>3)&0x70))

// ---- big 128x128 GEMM for qkv/out (unchanged, proven) ----
__global__ void __launch_bounds__(128) bf_gemm(
    const __nv_bfloat16* __restrict__ Ahi, const __nv_bfloat16* __restrict__ Alo,
    const __nv_bfloat16* __restrict__ BhiT, const __nv_bfloat16* __restrict__ BloT,
    int mode, const float* __restrict__ xres, const float* __restrict__ bias,
    float* __restrict__ outp)
{
    __shared__ __align__(1024) unsigned char sA[16384];
    __shared__ __align__(1024) unsigned char sB[16384];
    int t=threadIdx.x, lane=t&31, wid=t>>5;
    int g=lane>>2, tig=lane&3;
    int wm=wid&1, wn=wid>>1;
    int bn=blockIdx.x*128, bm=blockIdx.y*128;
    uint32_t sA32=cvta_s(sA), sB32=cvta_s(sB);
    int lrow=lane&15, lkh=(lane>>4)<<4;
    float acc[4][8][4];
    #pragma unroll
    for(int a=0;a<4;a++)
        #pragma unroll
        for(int b=0;b<8;b++)
            #pragma unroll
            for(int c=0;c<4;c++) acc[a][b][c]=0.f;
    for(int blk=0;blk<24;blk++){
        int seg=blk>>3, kb=(blk&7)<<6;
        const __nv_bfloat16* Asrc=(seg<2)?Ahi:Alo;
        const __nv_bfloat16* Bsrc=(seg==1)?BloT:BhiT;
        #pragma unroll
        for(int i=0;i<8;i++){
            int j=t+(i<<7); int row=j>>3, cg=j&7;
            uint4 v=*(const uint4*)(Asrc+(size_t)(bm+row)*512+kb+(cg<<3));
            *(uint4*)(sA+SWZ(row*128+(cg<<4)))=v;
        }
        #pragma unroll
        for(int i=0;i<8;i++){
            int j=t+(i<<7); int row=j>>3, cg=j&7;
            uint4 v=*(const uint4*)(Bsrc+(size_t)(bn+row)*512+kb+(cg<<3));
            *(uint4*)(sB+SWZ(row*128+(cg<<4)))=v;
        }
        __syncthreads();
        #pragma unroll
        for(int kc=0;kc<4;kc++){
            int kboff=kc*32+lkh;
            uint32_t af[4][4], bfr[8][2];
            #pragma unroll
            for(int mt=0;mt<4;mt++){
                uint32_t addr=sA32+SWZ((wm*64+mt*16+lrow)*128+kboff);
                LDSM4(af[mt], addr);
            }
            #pragma unroll
            for(int p=0;p<4;p++){
                uint32_t r4[4];
                uint32_t addr=sB32+SWZ((wn*64+p*16+lrow)*128+kboff);
                LDSM4(r4, addr);
                bfr[2*p][0]=r4[0]; bfr[2*p+1][0]=r4[1];
                bfr[2*p][1]=r4[2]; bfr[2*p+1][1]=r4[3];
            }
            #pragma unroll
            for(int mt=0;mt<4;mt++)
                #pragma unroll
                for(int nt=0;nt<8;nt++)
                    mma16816(acc[mt][nt], af[mt], bfr[nt]);
        }
        __syncthreads();
    }
    #pragma unroll
    for(int mt=0;mt<4;mt++)
        #pragma unroll
        for(int nt=0;nt<8;nt++)
            #pragma unroll
            for(int ci=0;ci<4;ci++){
                int row=bm+wm*64+mt*16+g+((ci>>1)<<3);
                int col=bn+wn*64+nt*8+(tig<<1)+(ci&1);
                float val=acc[mt][nt][ci];
                if(mode==0){
                    int b_=row>>13, n=row&8191;
                    int s=col>>9, inner=col&511, h=inner>>6, d=inner&63;
                    size_t o=((size_t)((b_*NH+h)*NTOK+n))*DH+d;
                    if(s==0) g_q[o]=val*0.125f;
                    else if(s==1) g_k[o]=val;
                    else g_v[o]=val;
                } else {
                    size_t o=(size_t)row*DIMX+col;
                    outp[o]=xres[o]+bias[col]+val;
                }
            }
}

// ---- flexible 128x64-tile bf16-split batched GEMM: C = A @ B^T ----
// A [bh][M][K] hi/lo (lda=K stride), B^T [bh][N][K] hi/lo.
// mode 0: Cout[bh*cStr + row*ldC + col] = val (fp32)
// mode 1: g_attn scatter-add (a1z2)
// mode 2: g_a3vp partial (split-K; z = ksp*16+bh)
__global__ void __launch_bounds__(128) bfg2(
    const __nv_bfloat16* __restrict__ Ahi_, const __nv_bfloat16* __restrict__ Alo_,
    size_t aStr, int lda,
    const __nv_bfloat16* __restrict__ Bhi_, const __nv_bfloat16* __restrict__ Blo_,
    size_t bStr, int ldb,
    int kspan, int useSplitK,
    float* __restrict__ Cout, size_t cStr, int ldC, int mode)
{
    __shared__ __align__(1024) unsigned char sA[16384];
    __shared__ __align__(1024) unsigned char sB[8192];
    int z=blockIdx.z;
    int bh, kbeg;
    if(useSplitK){ bh=z&15; kbeg=(z>>4)*kspan; } else { bh=z; kbeg=0; }
    const __nv_bfloat16* Ahi=Ahi_+(size_t)bh*aStr;
    const __nv_bfloat16* Alo=Alo_+(size_t)bh*aStr;
    const __nv_bfloat16* Bhi=Bhi_+(size_t)bh*bStr;
    const __nv_bfloat16* Blo=Blo_+(size_t)bh*bStr;
    int t=threadIdx.x, lane=t&31, wid=t>>5;
    int g=lane>>2, tig=lane&3;
    int wm=wid&1, wn=wid>>1;          // 2x2 warps; warp tile 64x32
    int bn=blockIdx.x*64, bm=blockIdx.y*128;
    uint32_t sA32=cvta_s(sA), sB32=cvta_s(sB);
    int lrow=lane&15, lkh=(lane>>4)<<4;
    float acc[4][4][4];
    #pragma unroll
    for(int a=0;a<4;a++)
        #pragma unroll
        for(int b=0;b<4;b++)
            #pragma unroll
            for(int c=0;c<4;c++) acc[a][b][c]=0.f;

    for(int pass=0;pass<3;pass++){
        const __nv_bfloat16* As=(pass<2)?Ahi:Alo;
        const __nv_bfloat16* Bs=(pass==1)?Blo:Bhi;
        for(int k0=kbeg;k0<kbeg+kspan;k0+=64){
            #pragma unroll
            for(int i=0;i<8;i++){
                int j=t+(i<<7); int row=j>>3, cg=j&7;
                uint4 v=*(const uint4*)(As+(size_t)(bm+row)*lda+k0+(cg<<3));
                *(uint4*)(sA+SWZ(row*128+(cg<<4)))=v;
            }
            #pragma unroll
            for(int i=0;i<4;i++){
                int j=t+(i<<7); int row=j>>3, cg=j&7;
                uint4 v=*(const uint4*)(Bs+(size_t)(bn+row)*ldb+k0+(cg<<3));
                *(uint4*)(sB+SWZ(row*128+(cg<<4)))=v;
            }
            __syncthreads();
            #pragma unroll
            for(int kc=0;kc<4;kc++){
                int kboff=kc*32+lkh;
                uint32_t af[4][4], bfr[4][2];
                #pragma unroll
                for(int mt=0;mt<4;mt++){
                    uint32_t addr=sA32+SWZ((wm*64+mt*16+lrow)*128+kboff);
                    LDSM4(af[mt], addr);
                }
                #pragma unroll
                for(int p=0;p<2;p++){
                    uint32_t r4[4];
                    uint32_t addr=sB32+SWZ((wn*32+p*16+lrow)*128+kboff);
                    LDSM4(r4, addr);
                    bfr[2*p][0]=r4[0]; bfr[2*p+1][0]=r4[1];
                    bfr[2*p][1]=r4[2]; bfr[2*p+1][1]=r4[3];
                }
                #pragma unroll
                for(int mt=0;mt<4;mt++)
                    #pragma unroll
                    for(int nt=0;nt<4;nt++)
                        mma16816(acc[mt][nt], af[mt], bfr[nt]);
            }
            __syncthreads();
        }
    }

    #pragma unroll
    for(int mt=0;mt<4;mt++)
        #pragma unroll
        for(int nt=0;nt<4;nt++)
            #pragma unroll
            for(int ci=0;ci<4;ci++){
                int row=bm+wm*64+mt*16+g+((ci>>1)<<3);
                int col=bn+wn*32+nt*8+(tig<<1)+(ci&1);
                float val=acc[mt][nt][ci];
                if(mode==0){
                    Cout[(size_t)bh*cStr+(size_t)row*ldC+col]=val;
                } else if(mode==1){
                    int b=bh>>3, h=bh&7;
                    g_attn[((size_t)(b*NTOK+row))*DIMX+h*64+col]+=val;
                } else {
                    g_a3vp[(size_t)z*ML*DH+(size_t)row*DH+col]=val;
                }
            }
}

// ---- conversions ----
__global__ void split2_kernel(const float* __restrict__ a, __nv_bfloat16* __restrict__ ahi,
                              __nv_bfloat16* __restrict__ alo,
                              const float* __restrict__ b, __nv_bfloat16* __restrict__ bhi2,
                              __nv_bfloat16* __restrict__ blo2){
    size_t i4=((size_t)blockIdx.x*256+threadIdx.x)*4;
    float4 va=*(const float4*)(a+i4);
    float4 vb=*(const float4*)(b+i4);
    float xa[4]={va.x,va.y,va.z,va.w}, xb[4]={vb.x,vb.y,vb.z,vb.w};
    #pragma unroll
    for(int j=0;j<4;j++){
        __nv_bfloat16 h=__float2bfloat16(xa[j]);
        ahi[i4+j]=h; alo[i4+j]=__float2bfloat16(xa[j]-__bfloat162float(h));
        __nv_bfloat16 h2=__float2bfloat16(xb[j]);
        bhi2[i4+j]=h2; blo2[i4+j]=__float2bfloat16(xb[j]-__bfloat162float(h2));
    }
}
// transpose+split: in [bh][R][C] fp32 -> out hi/lo [bh][C][R]
__global__ void tsplit_kernel(const float* __restrict__ in, size_t inStr,
                              __nv_bfloat16* __restrict__ ohi, __nv_bfloat16* __restrict__ olo,
                              size_t oStr, int R, int C){
    __shared__ float tile[32][33];
    int bh=blockIdx.z;
    int r0=blockIdx.x*32, c0=blockIdx.y*32;
    int tx=threadIdx.x&31, ty=threadIdx.x>>5;
    #pragma unroll
    for(int i=0;i<32;i+=8) tile[ty+i][tx]=in[(size_t)bh*inStr+(size_t)(r0+ty+i)*C+c0+tx];
    __syncthreads();
    #pragma unroll
    for(int i=0;i<32;i+=8){
        float v=tile[tx][ty+i];
        int c=c0+ty+i, r=r0+tx;
        __nv_bfloat16 h=__float2bfloat16(v);
        ohi[(size_t)bh*oStr+(size_t)c*R+r]=h;
        olo[(size_t)bh*oStr+(size_t)c*R+r]=__float2bfloat16(v-__bfloat162float(h));
    }
}

__global__ void wtrans_kernel(const float* __restrict__ W,
                              __nv_bfloat16* __restrict__ BhiT, __nv_bfloat16* __restrict__ BloT,
                              int K, int N){
    __shared__ float tile[32][33];
    int k0=blockIdx.y*32, n0=blockIdx.x*32;
    int tx=threadIdx.x&31, ty=threadIdx.x>>5;
    #pragma unroll
    for(int i=0;i<32;i+=8) tile[ty+i][tx]=W[(size_t)(k0+ty+i)*N+n0+tx];
    __syncthreads();
    #pragma unroll
    for(int i=0;i<32;i+=8){
        int n=n0+ty+i, k=k0+tx;
        float v=tile[tx][ty+i];
        __nv_bfloat16 h=__float2bfloat16(v);
        BhiT[(size_t)n*K+k]=h;
        BloT[(size_t)n*K+k]=__float2bfloat16(v-__bfloat162float(h));
    }
}

__global__ void a2bf_kernel(){
    size_t i4=((size_t)blockIdx.x*256+threadIdx.x)*4;
    float4 v=*(const float4*)(g_attn+i4);
    float xs[4]={v.x,v.y,v.z,v.w};
    #pragma unroll
    for(int j=0;j<4;j++){
        __nv_bfloat16 h=__float2bfloat16(xs[j]);
        g_bhi[i4+j]=h;
        g_blo[i4+j]=__float2bfloat16(xs[j]-__bfloat162float(h));
    }
}

__global__ void ln_kernel(const float* __restrict__ x, const float* __restrict__ w,
                          const float* __restrict__ bp){
    int row=blockIdx.x, t=threadIdx.x;
    const float* xr=x+(size_t)row*DIMX;
    float v0=xr[t], v1=xr[t+256];
    float s=v0+v1, sq=v0*v0+v1*v1;
    __shared__ float r1[8], r2[8];
    #pragma unroll
    for(int o=16;o;o>>=1){ s+=__shfl_xor_sync(~0u,s,o); sq+=__shfl_xor_sync(~0u,sq,o); }
    if((t&31)==0){ r1[t>>5]=s; r2[t>>5]=sq; }
    __syncthreads();
    float ss=0, qq=0;
    #pragma unroll
    for(int i=0;i<8;i++){ ss+=r1[i]; qq+=r2[i]; }
    float mean=ss*(1.f/512.f);
    float rstd=rsqrtf(qq*(1.f/512.f)-mean*mean+1e-5f);
    float y0=(v0-mean)*rstd*w[t]+bp[t];
    float y1=(v1-mean)*rstd*w[t+256]+bp[t+256];
    __nv_bfloat16 h0=__float2bfloat16(y0), h1=__float2bfloat16(y1);
    size_t b=(size_t)row*DIMX;
    g_bhi[b+t]=h0;      g_blo[b+t]=__float2bfloat16(y0-__bfloat162float(h0));
    g_bhi[b+t+256]=h1;  g_blo[b+t+256]=__float2bfloat16(y1-__bfloat162float(h1));
}

// ================= fp32 SIMT cores =================
__device__ __forceinline__ void loadA_kmajor(float (*As)[129], const float* __restrict__ Ag,
                                             int lda, int bm, int k0, int t){
    #pragma unroll
    for(int i=0;i<4;i++){
        int q=t+(i<<8); int r=q>>3; int kq=q&7;
        float4 v=*(const float4*)(Ag+(size_t)(bm+r)*lda+k0+(kq<<2));
        As[(kq<<2)+0][r]=v.x; As[(kq<<2)+1][r]=v.y;
        As[(kq<<2)+2][r]=v.z; As[(kq<<2)+3][r]=v.w;
    }
}
__device__ __forceinline__ void loadB_kn64(float (*Bs)[65], const float* __restrict__ Bg,
                                           int ldb, int bn, int k0, int t){
    #pragma unroll
    for(int i=0;i<2;i++){
        int q=t+(i<<8); int kk=q>>4; int cq=q&15;
        float4 v=*(const float4*)(Bg+(size_t)(k0+kk)*ldb+bn+(cq<<2));
        Bs[kk][(cq<<2)+0]=v.x; Bs[kk][(cq<<2)+1]=v.y;
        Bs[kk][(cq<<2)+2]=v.z; Bs[kk][(cq<<2)+3]=v.w;
    }
}
__device__ __forceinline__ void fma128(const float (*As)[129], const float (*Bs)[129],
                                       float acc[8][8], int tx, int ty){
    #pragma unroll
    for(int kk=0;kk<32;kk++){
        float a[8], b[8];
        #pragma unroll
        for(int i=0;i<8;i++) a[i]=As[kk][ty*8+i];
        #pragma unroll
        for(int j=0;j<8;j++) b[j]=Bs[kk][tx+(j<<4)];
        #pragma unroll
        for(int i=0;i<8;i++)
            #pragma unroll
            for(int j=0;j<8;j++) acc[i][j]+=a[i]*b[j];
    }
}
__device__ __forceinline__ void fma64(const float (*As)[129], const float (*Bs)[65],
                                      float acc[8][4], int tx, int ty){
    #pragma unroll
    for(int kk=0;kk<32;kk++){
        float a[8], b[4];
        #pragma unroll
        for(int i=0;i<8;i++) a[i]=As[kk][ty*8+i];
        #pragma unroll
        for(int j=0;j<4;j++) b[j]=Bs[kk][tx+(j<<4)];
        #pragma unroll
        for(int i=0;i<8;i++)
            #pragma unroll
            for(int j=0;j<4;j++) acc[i][j]+=a[i]*b[j];
    }
}

__global__ void landmark_kernel(){
    int blk=blockIdx.x, bh=blk>>8, m=blk&255, d=threadIdx.x;
    const float* qp=g_q+((size_t)(bh*NTOK+m*32))*DH+d;
    const float* kp=g_k+((size_t)(bh*NTOK+m*32))*DH+d;
    float sq=0,sk=0;
    #pragma unroll
    for(int j=0;j<32;j++){ sq+=qp[(size_t)j*DH]; sk+=kp[(size_t)j*DH]; }
    g_ql[(bh*ML+m)*DH+d]=sq*(1.f/32.f);
    g_kl[(bh*ML+m)*DH+d]=sk*(1.f/32.f);
}

__global__ void sim_kernel(const float* __restrict__ Abase, const float* __restrict__ Bbase,
                           float* __restrict__ Cbase, size_t aBH, size_t bBH, size_t cBH, int ldC){
    __shared__ float As[32][129], Bs[32][129];
    int t=threadIdx.x, tx=t&15, ty=t>>4;
    int bh=blockIdx.z;
    int bn=blockIdx.x*128, bm=blockIdx.y*128;
    const float* A=Abase+(size_t)bh*aBH;
    const float* B=Bbase+(size_t)bh*bBH;
    float* C=Cbase+(size_t)bh*cBH;
    float acc[8][8]={};
    for(int k0=0;k0<64;k0+=32){
        loadA_kmajor(As, A, DH, bm, k0, t);
        loadA_kmajor(Bs, B, DH, bn, k0, t);
        __syncthreads();
        fma128(As,Bs,acc,tx,ty);
        __syncthreads();
    }
    #pragma unroll
    for(int i=0;i<8;i++)
        #pragma unroll
        for(int j=0;j<8;j++)
            C[(size_t)(bm+ty*8+i)*ldC+bn+tx+(j<<4)]=acc[i][j];
}

__global__ void softmax256_kernel(float* __restrict__ base){
    int w=threadIdx.x>>5, lane=threadIdx.x&31;
    size_t row=(size_t)blockIdx.x*8+w;
    float* p=base+row*ML;
    float4 v0=*(float4*)(p+lane*8);
    float4 v1=*(float4*)(p+lane*8+4);
    float mx=fmaxf(fmaxf(fmaxf(v0.x,v0.y),fmaxf(v0.z,v0.w)),
                   fmaxf(fmaxf(v1.x,v1.y),fmaxf(v1.z,v1.w)));
    #pragma unroll
    for(int o=16;o;o>>=1) mx=fmaxf(mx,__shfl_xor_sync(~0u,mx,o));
    v0.x=__expf(v0.x-mx); v0.y=__expf(v0.y-mx); v0.z=__expf(v0.z-mx); v0.w=__expf(v0.w-mx);
    v1.x=__expf(v1.x-mx); v1.y=__expf(v1.y-mx); v1.z=__expf(v1.z-mx); v1.w=__expf(v1.w-mx);
    float s=v0.x+v0.y+v0.z+v0.w+v1.x+v1.y+v1.z+v1.w;
    #pragma unroll
    for(int o=16;o;o>>=1) s+=__shfl_xor_sync(~0u,s,o);
    float inv=1.f/s;
    v0.x*=inv; v0.y*=inv; v0.z*=inv; v0.w*=inv;
    v1.x*=inv; v1.y*=inv; v1.z*=inv; v1.w*=inv;
    *(float4*)(p+lane*8)=v0;
    *(float4*)(p+lane*8+4)=v1;
}

// softmax over rows of 256, output bf16 hi/lo (for a1)
__global__ void softmax1bf_kernel(){
    int w=threadIdx.x>>5, lane=threadIdx.x&31;
    size_t row=(size_t)blockIdx.x*8+w;
    const float* p=g_sim3+row*ML;
    float v[8];
    #pragma unroll
    for(int i=0;i<8;i++) v[i]=p[lane*8+i];
    float mx=v[0];
    #pragma unroll
    for(int i=1;i<8;i++) mx=fmaxf(mx,v[i]);
    #pragma unroll
    for(int o=16;o;o>>=1) mx=fmaxf(mx,__shfl_xor_sync(~0u,mx,o));
    float s=0;
    #pragma unroll
    for(int i=0;i<8;i++){ v[i]=__expf(v[i]-mx); s+=v[i]; }
    #pragma unroll
    for(int o=16;o;o>>=1) s+=__shfl_xor_sync(~0u,s,o);
    float inv=1.f/s;
    #pragma unroll
    for(int i=0;i<8;i++){
        float val=v[i]*inv;
        __nv_bfloat16 h=__float2bfloat16(val);
        g_a3hi[row*ML+lane*8+i]=h;
        g_a3lo[row*ML+lane*8+i]=__float2bfloat16(val-__bfloat162float(h));
    }
}

// softmax over rows of 8192, output bf16 hi/lo (for a3)
__global__ void softmax3bf_kernel(){
    int row=blockIdx.x, t=threadIdx.x;
    const float* p=g_sim3+(size_t)row*NTOK;
    float v[32], mx=-3.0e38f;
    #pragma unroll
    for(int i=0;i<32;i++){ v[i]=p[t+(i<<8)]; mx=fmaxf(mx,v[i]); }
    __shared__ float red[8];
    #pragma unroll
    for(int o=16;o;o>>=1) mx=fmaxf(mx,__shfl_xor_sync(~0u,mx,o));
    if((t&31)==0) red[t>>5]=mx;
    __syncthreads();
    mx=red[0];
    #pragma unroll
    for(int k=1;k<8;k++) mx=fmaxf(mx,red[k]);
    float s=0;
    #pragma unroll
    for(int i=0;i<32;i++){ v[i]=__expf(v[i]-mx); s+=v[i]; }
    #pragma unroll
    for(int o=16;o;o>>=1) s+=__shfl_xor_sync(~0u,s,o);
    __syncthreads();
    if((t&31)==0) red[t>>5]=s;
    __syncthreads();
    s=0;
    #pragma unroll
    for(int k=0;k<8;k++) s+=red[k];
    float inv=1.f/s;
    size_t base=(size_t)row*NTOK;
    #pragma unroll
    for(int i=0;i<32;i++){
        float val=v[i]*inv;
        __nv_bfloat16 h=__float2bfloat16(val);
        g_a3hi[base+t+(i<<8)]=h;
        g_a3lo[base+t+(i<<8)]=__float2bfloat16(val-__bfloat162float(h));
    }
}

__global__ void scal_reset_kernel(){ g_scal[0]=0.f; g_scal[1]=0.f; }

__global__ void pinv_sums_kernel(){
    int bh=blockIdx.x, t=threadIdx.x;
    const float* A=g_a2+((size_t)bh<<16);
    float rs=0, cs=0;
    const float4* Ar=(const float4*)(A+(size_t)t*ML);
    #pragma unroll
    for(int j=0;j<64;j++){ float4 v=Ar[j]; rs+=fabsf(v.x)+fabsf(v.y)+fabsf(v.z)+fabsf(v.w); }
    for(int j=0;j<ML;j++) cs+=fabsf(A[(size_t)j*ML+t]);
    #pragma unroll
    for(int o=16;o;o>>=1){ rs=fmaxf(rs,__shfl_xor_sync(~0u,rs,o)); cs=fmaxf(cs,__shfl_xor_sync(~0u,cs,o)); }
    __shared__ float r1[8], r2[8];
    if((t&31)==0){ r1[t>>5]=rs; r2[t>>5]=cs; }
    __syncthreads();
    if(t==0){
        float m1=r1[0], m2=r2[0];
        #pragma unroll
        for(int k=1;k<8;k++){ m1=fmaxf(m1,r1[k]); m2=fmaxf(m2,r2[k]); }
        atomicMax((int*)&g_scal[0], __float_as_int(m1));
        atomicMax((int*)&g_scal[1], __float_as_int(m2));
    }
}

__global__ void zinit_kernel(){
    int e=blockIdx.x*256+threadIdx.x;
    float inv=1.f/(g_scal[0]*g_scal[1]);
    int bh=e>>16, r=(e>>8)&255, c=e&255;
    g_z0[e]=g_a2[(bh<<16)+(c<<8)+r]*inv;
}

__global__ void __launch_bounds__(128) mm256_kernel(
        const float* __restrict__ Ag, const float* __restrict__ Bg,
        float* __restrict__ Cg, float cdiag, float alpha){
    int bh=blockIdx.x;
    const float* A=Ag+((size_t)bh<<16);
    const float* B=Bg+((size_t)bh<<16);
    float* C=Cg+((size_t)bh<<16);
    int bm=blockIdx.y*64, bn=blockIdx.z*64;
    __shared__ float As[32][65], Bs[32][65];
    int t=threadIdx.x, tx=t&15, ty=t>>4;
    float acc[8][4]={};
    for(int k0=0;k0<256;k0+=32){
        #pragma unroll
        for(int i=0;i<4;i++){
            int j=t+(i<<7); int r=j>>3, kq=j&7;
            float4 v=*(const float4*)(A+(size_t)(bm+r)*256+k0+(kq<<2));
            As[(kq<<2)+0][r]=v.x; As[(kq<<2)+1][r]=v.y;
            As[(kq<<2)+2][r]=v.z; As[(kq<<2)+3][r]=v.w;
        }
        #pragma unroll
        for(int i=0;i<16;i++){
            int j=t+(i<<7); int kk=j>>6, c=j&63;
            int gk=k0+kk, gc=bn+c;
            float bv=B[(size_t)gk*256+gc];
            Bs[kk][c]=(gk==gc)?(cdiag-bv):(-bv);
        }
        __syncthreads();
        #pragma unroll
        for(int kk=0;kk<32;kk++){
            float a[8], b[4];
            #pragma unroll
            for(int i=0;i<8;i++) a[i]=As[kk][ty*8+i];
            #pragma unroll
            for(int j=0;j<4;j++) b[j]=Bs[kk][tx+(j<<4)];
            #pragma unroll
            for(int i=0;i<8;i++)
                #pragma unroll
                for(int j=0;j<4;j++) acc[i][j]+=a[i]*b[j];
        }
        __syncthreads();
    }
    #pragma unroll
    for(int i=0;i<8;i++)
        #pragma unroll
        for(int j=0;j<4;j++)
            C[(size_t)(bm+ty*8+i)*256+bn+tx+(j<<4)]=alpha*acc[i][j];
}

__global__ void a3v_reduce_kernel(){
    int e=blockIdx.x*256+threadIdx.x;
    float s=0;
    #pragma unroll
    for(int k=0;k<8;k++) s+=g_a3vp[(size_t)k*BHN*ML*DH+e];
    g_a3v[e]=s;
}

__global__ void z2_kernel(){
    __shared__ float As[32][129], Bs[32][65];
    int bm=blockIdx.x*128, bh=blockIdx.y;
    const float* A=g_z0+((size_t)bh<<16);
    const float* Bp=g_a3v+(size_t)bh*ML*DH;
    int t=threadIdx.x, tx=t&15, ty=t>>4;
    float acc[8][4]={};
    for(int k0=0;k0<256;k0+=32){
        loadA_kmajor(As, A, ML, bm, k0, t);
        loadB_kn64(Bs, Bp, DH, 0, k0, t);
        __syncthreads();
        fma64(As,Bs,acc,tx,ty);
        __syncthreads();
    }
    #pragma unroll
    for(int i=0;i<8;i++)
        #pragma unroll
        for(int j=0;j<4;j++)
            g_Z2[(size_t)bh*ML*DH+(bm+ty*8+i)*DH+tx+(j<<4)]=acc[i][j];
}

__global__ void conv_kernel(const float* __restrict__ cw){
    int idx=blockIdx.x*256+threadIdx.x;
    int d=idx&63, n=(idx>>6)&8191, bh=idx>>19;
    int h=bh&7;
    const float* vp=g_v+(size_t)bh*NTOK*DH+d;
    float s=0;
    #pragma unroll
    for(int kk=0;kk<33;kk++){
        int j=n+kk-16;
        if(j>=0 && j<NTOK) s+=cw[h*33+kk]*vp[(size_t)j*DH];
    }
    g_attn[((size_t)((bh>>3)*NTOK+n))*DIMX+h*64+d]=s;
}

extern "C" void kernel_launch(void* const* d_in, const int* in_sizes, int n_in,
                              void* d_out, int out_size){
    const float* x    = (const float*)d_in[0];
    const float* ln_w = (const float*)d_in[2];
    const float* ln_b = (const float*)d_in[3];
    const float* wqkv = (const float*)d_in[4];
    const float* wout = (const float*)d_in[5];
    const float* bout = (const float*)d_in[6];
    const float* cw   = (const float*)d_in[7];
    float* out = (float*)d_out;

    float *z0,*z1,*a2p,*xz,*t1,*t2,*qlp,*klp,*qp,*kp,*vp,*sim3p,*Z2p;
    __nv_bfloat16 *bhi,*blo,*wqhi,*wqlo,*wohi,*wolo;
    __nv_bfloat16 *qhi,*qlo,*khi,*klo,*qlhi,*qllo,*klhi,*kllo,*vthi,*vtlo,*z2thi,*z2tlo,*a3hi,*a3lo;
    cudaGetSymbolAddress((void**)&z0, g_z0);
    cudaGetSymbolAddress((void**)&z1, g_z1);
    cudaGetSymbolAddress((void**)&a2p, g_a2);
    cudaGetSymbolAddress((void**)&xz, g_xz);
    cudaGetSymbolAddress((void**)&t1, g_t1);
    cudaGetSymbolAddress((void**)&t2, g_t2);
    cudaGetSymbolAddress((void**)&qlp, g_ql);
    cudaGetSymbolAddress((void**)&klp, g_kl);
    cudaGetSymbolAddress((void**)&qp, g_q);
    cudaGetSymbolAddress((void**)&kp, g_k);
    cudaGetSymbolAddress((void**)&vp, g_v);
    cudaGetSymbolAddress((void**)&sim3p, g_sim3);
    cudaGetSymbolAddress((void**)&Z2p, g_Z2);
    cudaGetSymbolAddress((void**)&bhi, g_bhi);
    cudaGetSymbolAddress((void**)&blo, g_blo);
    cudaGetSymbolAddress((void**)&wqhi, g_wqhi);
    cudaGetSymbolAddress((void**)&wqlo, g_wqlo);
    cudaGetSymbolAddress((void**)&wohi, g_wohi);
    cudaGetSymbolAddress((void**)&wolo, g_wolo);
    cudaGetSymbolAddress((void**)&qhi, g_qhi);
    cudaGetSymbolAddress((void**)&qlo, g_qlo);
    cudaGetSymbolAddress((void**)&khi, g_khi);
    cudaGetSymbolAddress((void**)&klo, g_klo);
    cudaGetSymbolAddress((void**)&qlhi, g_qlhi);
    cudaGetSymbolAddress((void**)&qllo, g_qllo);
    cudaGetSymbolAddress((void**)&klhi, g_klhi);
    cudaGetSymbolAddress((void**)&kllo, g_kllo);
    cudaGetSymbolAddress((void**)&vthi, g_vthi);
    cudaGetSymbolAddress((void**)&vtlo, g_vtlo);
    cudaGetSymbolAddress((void**)&z2thi, g_z2thi);
    cudaGetSymbolAddress((void**)&z2tlo, g_z2tlo);
    cudaGetSymbolAddress((void**)&a3hi, g_a3hi);
    cudaGetSymbolAddress((void**)&a3lo, g_a3lo);

    wtrans_kernel<<<dim3(48,16), 256>>>(wqkv, wqhi, wqlo, 512, 1536);
    wtrans_kernel<<<dim3(16,16), 256>>>(wout, wohi, wolo, 512, 512);
    ln_kernel<<<BB*NTOK, 256>>>(x, ln_w, ln_b);
    bf_gemm<<<dim3(12,128), 128>>>(bhi, blo, wqhi, wqlo, 0, nullptr, nullptr, nullptr);
    landmark_kernel<<<BHN*ML, 64>>>();

    // conversions for attention GEMMs
    split2_kernel<<<BHN*NTOK*DH/1024, 256>>>(qp, qhi, qlo, kp, khi, klo);
    split2_kernel<<<BHN*ML*DH/1024, 256>>>(qlp, qlhi, qllo, klp, klhi, kllo);
    tsplit_kernel<<<dim3(256,2,BHN), 256>>>(vp, (size_t)NTOK*DH, vthi, vtlo, (size_t)DH*NTOK, NTOK, DH);

    // a2 = softmax(ql @ kl^T)  (fp32 path)
    sim_kernel<<<dim3(2,2,BHN), 256>>>(qlp, klp, a2p,
        (size_t)ML*DH, (size_t)ML*DH, (size_t)ML*ML, ML);
    softmax256_kernel<<<BHN*ML/8, 256>>>(a2p);

    scal_reset_kernel<<<1,1>>>();
    pinv_sums_kernel<<<BHN, 256>>>();
    zinit_kernel<<<4096, 256>>>();
    float* zc=z0; float* za=z1;
    for(int it=0; it<6; it++){
        mm256_kernel<<<dim3(BHN,4,4),128>>>(a2p, zc, xz, 0.f, -1.f);
        mm256_kernel<<<dim3(BHN,4,4),128>>>(xz, xz, t1, 7.f, 1.f);
        mm256_kernel<<<dim3(BHN,4,4),128>>>(xz, t1, t2, 15.f, 1.f);
        mm256_kernel<<<dim3(BHN,4,4),128>>>(zc, t2, za, 13.f, 0.25f);
        float* tmp=zc; zc=za; za=tmp;
    }

    // sim3 = ql @ k^T  (bf16 mma)
    bfg2<<<dim3(128,2,BHN), 128>>>(qlhi, qllo, (size_t)ML*DH, DH,
        khi, klo, (size_t)NTOK*DH, DH, 64, 0, sim3p, (size_t)ML*NTOK, NTOK, 0);
    softmax3bf_kernel<<<BHN*ML, 256>>>();
    // a3 @ v  (split-K bf16)
    bfg2<<<dim3(1,2,128), 128>>>(a3hi, a3lo, (size_t)ML*NTOK, NTOK,
        vthi, vtlo, (size_t)DH*NTOK, NTOK, 1024, 1, nullptr, 0, 0, 2);
    a3v_reduce_kernel<<<1024, 256>>>();
    z2_kernel<<<dim3(2,BHN), 256>>>();
    tsplit_kernel<<<dim3(8,2,BHN), 256>>>(Z2p, (size_t)ML*DH, z2thi, z2tlo, (size_t)DH*ML, ML, DH);
    conv_kernel<<<32768, 256>>>(cw);

    // sim1 = q @ kl^T  (bf16 mma)
    bfg2<<<dim3(4,64,BHN), 128>>>(qhi, qlo, (size_t)NTOK*DH, DH,
        klhi, kllo, (size_t)ML*DH, DH, 64, 0, sim3p, (size_t)NTOK*ML, ML, 0);
    softmax1bf_kernel<<<BHN*NTOK/8, 256>>>();
    // g_attn += a1 @ Z2  (bf16 mma)
    bfg2<<<dim3(1,64,BHN), 128>>>(a3hi, a3lo, (size_t)NTOK*ML, ML,
        z2thi, z2tlo, (size_t)DH*ML, ML, 256, 0, nullptr, 0, 0, 1);

    a2bf_kernel<<<8192, 256>>>();
    bf_gemm<<<dim3(4,128), 128>>>(bhi, blo, wohi, wolo, 1, x, bout, out);
}

// round 14
// speedup vs baseline: 1.1407x; 1.1407x over previous
#include <cuda_runtime.h>
#include <cuda_bf16.h>
#include <math.h>
#include <stdint.h>

#define BB 2
#define NTOK 8192
#define DIMX 512
#define NH 8
#define DH 64
#define ML 256
#define BHN 16

__device__ float g_q [BHN*NTOK*DH];
__device__ float g_k [BHN*NTOK*DH];
__device__ float g_v [BHN*NTOK*DH];
__device__ float g_ql[BHN*ML*DH];
__device__ float g_kl[BHN*ML*DH];
__device__ float g_a2[BHN*ML*ML];
__device__ float g_z0[BHN*ML*ML];
__device__ float g_z1[BHN*ML*ML];
__device__ float g_xz[BHN*ML*ML];
__device__ float g_t1[BHN*ML*ML];
__device__ float g_t2[BHN*ML*ML];
__device__ float g_sim3[(size_t)BHN*ML*NTOK];
__device__ float g_a3vp[8*BHN*ML*DH];
__device__ float g_a3v [BHN*ML*DH];
__device__ float g_Z2  [BHN*ML*DH];
__device__ float g_attn[BB*NTOK*DIMX];
__device__ float g_scal[2];
__device__ __nv_bfloat16 g_bhi[BB*NTOK*DIMX];
__device__ __nv_bfloat16 g_blo[BB*NTOK*DIMX];
__device__ __nv_bfloat16 g_wqhi[1536*512];
__device__ __nv_bfloat16 g_wqlo[1536*512];
__device__ __nv_bfloat16 g_wohi[512*512];
__device__ __nv_bfloat16 g_wolo[512*512];

// ================= bf16 mma.sync + ldmatrix + cp.async =================
__device__ __forceinline__ void mma16816(float* c, const uint32_t* a, const uint32_t* b){
    asm volatile("mma.sync.aligned.m16n8k16.row.col.f32.bf16.bf16.f32 "
        "{%0,%1,%2,%3},{%4,%5,%6,%7},{%8,%9},{%0,%1,%2,%3};"
        : "+f"(c[0]),"+f"(c[1]),"+f"(c[2]),"+f"(c[3])
        : "r"(a[0]),"r"(a[1]),"r"(a[2]),"r"(a[3]),"r"(b[0]),"r"(b[1]));
}
__device__ __forceinline__ uint32_t cvta_s(const void* p){
    uint32_t a;
    asm("{ .reg .u64 t; cvta.to.shared.u64 t, %1; cvt.u32.u64 %0, t; }" : "=r"(a) : "l"(p));
    return a;
}
#define LDSM4(r, a) \
    asm volatile("ldmatrix.sync.aligned.m8n8.x4.shared.b16 {%0,%1,%2,%3}, [%4];" \
        : "=r"((r)[0]),"=r"((r)[1]),"=r"((r)[2]),"=r"((r)[3]) : "r"(a))
#define SWZ(o) ((o) ^ (((o)>>3)&0x70))
#define CPA16(dst, src) \
    asm volatile("cp.async.cg.shared.global [%0], [%1], 16;" :: "r"(dst), "l"(src))
#define CPA_COMMIT() asm volatile("cp.async.commit_group;")
#define CPA_WAIT1() asm volatile("cp.async.wait_group 1;")
#define CPA_WAIT0() asm volatile("cp.async.wait_group 0;")

__device__ __forceinline__ void bf_stage_issue(
    uint32_t sAb, uint32_t sBb,
    const __nv_bfloat16* __restrict__ Asrc, const __nv_bfloat16* __restrict__ Bsrc,
    int bm, int bn, int kb, int t)
{
    #pragma unroll
    for(int i=0;i<8;i++){
        int j=t+(i<<7); int row=j>>3, cg=j&7;
        CPA16(sAb+SWZ(row*128+(cg<<4)), Asrc+(size_t)(bm+row)*512+kb+(cg<<3));
    }
    #pragma unroll
    for(int i=0;i<8;i++){
        int j=t+(i<<7); int row=j>>3, cg=j&7;
        CPA16(sBb+SWZ(row*128+(cg<<4)), Bsrc+(size_t)(bn+row)*512+kb+(cg<<3));
    }
    CPA_COMMIT();
}

// bf16-split GEMM: C[128x128] = A @ B^T over Keff = 3*512, double-buffered cp.async.
// mode 0: qkv scatter; mode 1: out = x + bias + C.
__global__ void __launch_bounds__(128) bf_gemm(
    const __nv_bfloat16* __restrict__ Ahi, const __nv_bfloat16* __restrict__ Alo,
    const __nv_bfloat16* __restrict__ BhiT, const __nv_bfloat16* __restrict__ BloT,
    int mode, const float* __restrict__ xres, const float* __restrict__ bias,
    float* __restrict__ outp)
{
    extern __shared__ __align__(1024) unsigned char dyns[];
    int t=threadIdx.x, lane=t&31, wid=t>>5;
    int g=lane>>2, tig=lane&3;
    int wm=wid&1, wn=wid>>1;
    int bn=blockIdx.x*128, bm=blockIdx.y*128;
    uint32_t base=cvta_s(dyns);
    uint32_t sA32[2]={base, base+32768u};
    uint32_t sB32[2]={base+16384u, base+49152u};
    int lrow=lane&15, lkh=(lane>>4)<<4;
    float acc[4][8][4];
    #pragma unroll
    for(int a=0;a<4;a++)
        #pragma unroll
        for(int b=0;b<8;b++)
            #pragma unroll
            for(int c=0;c<4;c++) acc[a][b][c]=0.f;

    // stage 0 prologue
    {
        const __nv_bfloat16* Asrc=Ahi;
        const __nv_bfloat16* Bsrc=BhiT;
        bf_stage_issue(sA32[0], sB32[0], Asrc, Bsrc, bm, bn, 0, t);
    }
    for(int blk=0;blk<24;blk++){
        if(blk+1<24){
            int nb=blk+1;
            int seg=nb>>3, kb=(nb&7)<<6;
            const __nv_bfloat16* Asrc=(seg<2)?Ahi:Alo;
            const __nv_bfloat16* Bsrc=(seg==1)?BloT:BhiT;
            bf_stage_issue(sA32[nb&1], sB32[nb&1], Asrc, Bsrc, bm, bn, kb, t);
            CPA_WAIT1();
        } else {
            CPA_WAIT0();
        }
        __syncthreads();
        int buf=blk&1;
        #pragma unroll
        for(int kc=0;kc<4;kc++){
            int kboff=kc*32+lkh;
            uint32_t af[4][4], bfr[8][2];
            #pragma unroll
            for(int mt=0;mt<4;mt++){
                uint32_t addr=sA32[buf]+SWZ((wm*64+mt*16+lrow)*128+kboff);
                LDSM4(af[mt], addr);
            }
            #pragma unroll
            for(int p=0;p<4;p++){
                uint32_t r4[4];
                uint32_t addr=sB32[buf]+SWZ((wn*64+p*16+lrow)*128+kboff);
                LDSM4(r4, addr);
                bfr[2*p][0]=r4[0]; bfr[2*p+1][0]=r4[1];
                bfr[2*p][1]=r4[2]; bfr[2*p+1][1]=r4[3];
            }
            #pragma unroll
            for(int mt=0;mt<4;mt++)
                #pragma unroll
                for(int nt=0;nt<8;nt++)
                    mma16816(acc[mt][nt], af[mt], bfr[nt]);
        }
        __syncthreads();
    }

    #pragma unroll
    for(int mt=0;mt<4;mt++)
        #pragma unroll
        for(int nt=0;nt<8;nt++)
            #pragma unroll
            for(int ci=0;ci<4;ci++){
                int row=bm+wm*64+mt*16+g+((ci>>1)<<3);
                int col=bn+wn*64+nt*8+(tig<<1)+(ci&1);
                float val=acc[mt][nt][ci];
                if(mode==0){
                    int b_=row>>13, n=row&8191;
                    int s=col>>9, inner=col&511, h=inner>>6, d=inner&63;
                    size_t o=((size_t)((b_*NH+h)*NTOK+n))*DH+d;
                    if(s==0) g_q[o]=val*0.125f;
                    else if(s==1) g_k[o]=val;
                    else g_v[o]=val;
                } else {
                    size_t o=(size_t)row*DIMX+col;
                    outp[o]=xres[o]+bias[col]+val;
                }
            }
}

// ---- weight transpose + bf16 hi/lo split ----
__global__ void wtrans_kernel(const float* __restrict__ W,
                              __nv_bfloat16* __restrict__ BhiT, __nv_bfloat16* __restrict__ BloT,
                              int K, int N){
    __shared__ float tile[32][33];
    int k0=blockIdx.y*32, n0=blockIdx.x*32;
    int tx=threadIdx.x&31, ty=threadIdx.x>>5;
    #pragma unroll
    for(int i=0;i<32;i+=8) tile[ty+i][tx]=W[(size_t)(k0+ty+i)*N+n0+tx];
    __syncthreads();
    #pragma unroll
    for(int i=0;i<32;i+=8){
        int n=n0+ty+i, k=k0+tx;
        float v=tile[tx][ty+i];
        __nv_bfloat16 h=__float2bfloat16(v);
        BhiT[(size_t)n*K+k]=h;
        BloT[(size_t)n*K+k]=__float2bfloat16(v-__bfloat162float(h));
    }
}

__global__ void a2bf_kernel(){
    size_t i4=((size_t)blockIdx.x*256+threadIdx.x)*4;
    float4 v=*(const float4*)(g_attn+i4);
    float xs[4]={v.x,v.y,v.z,v.w};
    #pragma unroll
    for(int j=0;j<4;j++){
        __nv_bfloat16 h=__float2bfloat16(xs[j]);
        g_bhi[i4+j]=h;
        g_blo[i4+j]=__float2bfloat16(xs[j]-__bfloat162float(h));
    }
}

__global__ void ln_kernel(const float* __restrict__ x, const float* __restrict__ w,
                          const float* __restrict__ bp){
    int row=blockIdx.x, t=threadIdx.x;
    const float* xr=x+(size_t)row*DIMX;
    float v0=xr[t], v1=xr[t+256];
    float s=v0+v1, sq=v0*v0+v1*v1;
    __shared__ float r1[8], r2[8];
    #pragma unroll
    for(int o=16;o;o>>=1){ s+=__shfl_xor_sync(~0u,s,o); sq+=__shfl_xor_sync(~0u,sq,o); }
    if((t&31)==0){ r1[t>>5]=s; r2[t>>5]=sq; }
    __syncthreads();
    float ss=0, qq=0;
    #pragma unroll
    for(int i=0;i<8;i++){ ss+=r1[i]; qq+=r2[i]; }
    float mean=ss*(1.f/512.f);
    float rstd=rsqrtf(qq*(1.f/512.f)-mean*mean+1e-5f);
    float y0=(v0-mean)*rstd*w[t]+bp[t];
    float y1=(v1-mean)*rstd*w[t+256]+bp[t+256];
    __nv_bfloat16 h0=__float2bfloat16(y0), h1=__float2bfloat16(y1);
    size_t b=(size_t)row*DIMX;
    g_bhi[b+t]=h0;      g_blo[b+t]=__float2bfloat16(y0-__bfloat162float(h0));
    g_bhi[b+t+256]=h1;  g_blo[b+t+256]=__float2bfloat16(y1-__bfloat162float(h1));
}

// ================= fp32 SIMT cores =================
__device__ __forceinline__ void loadA_kmajor(float (*As)[129], const float* __restrict__ Ag,
                                             int lda, int bm, int k0, int t){
    #pragma unroll
    for(int i=0;i<4;i++){
        int q=t+(i<<8); int r=q>>3; int kq=q&7;
        float4 v=*(const float4*)(Ag+(size_t)(bm+r)*lda+k0+(kq<<2));
        As[(kq<<2)+0][r]=v.x; As[(kq<<2)+1][r]=v.y;
        As[(kq<<2)+2][r]=v.z; As[(kq<<2)+3][r]=v.w;
    }
}
__device__ __forceinline__ void loadB_kn64(float (*Bs)[65], const float* __restrict__ Bg,
                                           int ldb, int bn, int k0, int t){
    #pragma unroll
    for(int i=0;i<2;i++){
        int q=t+(i<<8); int kk=q>>4; int cq=q&15;
        float4 v=*(const float4*)(Bg+(size_t)(k0+kk)*ldb+bn+(cq<<2));
        Bs[kk][(cq<<2)+0]=v.x; Bs[kk][(cq<<2)+1]=v.y;
        Bs[kk][(cq<<2)+2]=v.z; Bs[kk][(cq<<2)+3]=v.w;
    }
}
__device__ __forceinline__ void fma128(const float (*As)[129], const float (*Bs)[129],
                                       float acc[8][8], int tx, int ty){
    #pragma unroll
    for(int kk=0;kk<32;kk++){
        float a[8], b[8];
        #pragma unroll
        for(int i=0;i<8;i++) a[i]=As[kk][ty*8+i];
        #pragma unroll
        for(int j=0;j<8;j++) b[j]=Bs[kk][tx+(j<<4)];
        #pragma unroll
        for(int i=0;i<8;i++)
            #pragma unroll
            for(int j=0;j<8;j++) acc[i][j]+=a[i]*b[j];
    }
}
__device__ __forceinline__ void fma64(const float (*As)[129], const float (*Bs)[65],
                                      float acc[8][4], int tx, int ty){
    #pragma unroll
    for(int kk=0;kk<32;kk++){
        float a[8], b[4];
        #pragma unroll
        for(int i=0;i<8;i++) a[i]=As[kk][ty*8+i];
        #pragma unroll
        for(int j=0;j<4;j++) b[j]=Bs[kk][tx+(j<<4)];
        #pragma unroll
        for(int i=0;i<8;i++)
            #pragma unroll
            for(int j=0;j<4;j++) acc[i][j]+=a[i]*b[j];
    }
}

__global__ void landmark_kernel(){
    int blk=blockIdx.x, bh=blk>>8, m=blk&255, d=threadIdx.x;
    const float* qp=g_q+((size_t)(bh*NTOK+m*32))*DH+d;
    const float* kp=g_k+((size_t)(bh*NTOK+m*32))*DH+d;
    float sq=0,sk=0;
    #pragma unroll
    for(int j=0;j<32;j++){ sq+=qp[(size_t)j*DH]; sk+=kp[(size_t)j*DH]; }
    g_ql[(bh*ML+m)*DH+d]=sq*(1.f/32.f);
    g_kl[(bh*ML+m)*DH+d]=sk*(1.f/32.f);
}

__global__ void sim_kernel(const float* __restrict__ Abase, const float* __restrict__ Bbase,
                           float* __restrict__ Cbase, size_t aBH, size_t bBH, size_t cBH, int ldC){
    __shared__ float As[32][129], Bs[32][129];
    int t=threadIdx.x, tx=t&15, ty=t>>4;
    int bh=blockIdx.z;
    int bn=blockIdx.x*128, bm=blockIdx.y*128;
    const float* A=Abase+(size_t)bh*aBH;
    const float* B=Bbase+(size_t)bh*bBH;
    float* C=Cbase+(size_t)bh*cBH;
    float acc[8][8]={};
    for(int k0=0;k0<64;k0+=32){
        loadA_kmajor(As, A, DH, bm, k0, t);
        loadA_kmajor(Bs, B, DH, bn, k0, t);
        __syncthreads();
        fma128(As,Bs,acc,tx,ty);
        __syncthreads();
    }
    #pragma unroll
    for(int i=0;i<8;i++)
        #pragma unroll
        for(int j=0;j<8;j++)
            C[(size_t)(bm+ty*8+i)*ldC+bn+tx+(j<<4)]=acc[i][j];
}

__global__ void softmax256_kernel(float* __restrict__ base){
    int w=threadIdx.x>>5, lane=threadIdx.x&31;
    size_t row=(size_t)blockIdx.x*8+w;
    float* p=base+row*ML;
    float4 v0=*(float4*)(p+lane*8);
    float4 v1=*(float4*)(p+lane*8+4);
    float mx=fmaxf(fmaxf(fmaxf(v0.x,v0.y),fmaxf(v0.z,v0.w)),
                   fmaxf(fmaxf(v1.x,v1.y),fmaxf(v1.z,v1.w)));
    #pragma unroll
    for(int o=16;o;o>>=1) mx=fmaxf(mx,__shfl_xor_sync(~0u,mx,o));
    v0.x=__expf(v0.x-mx); v0.y=__expf(v0.y-mx); v0.z=__expf(v0.z-mx); v0.w=__expf(v0.w-mx);
    v1.x=__expf(v1.x-mx); v1.y=__expf(v1.y-mx); v1.z=__expf(v1.z-mx); v1.w=__expf(v1.w-mx);
    float s=v0.x+v0.y+v0.z+v0.w+v1.x+v1.y+v1.z+v1.w;
    #pragma unroll
    for(int o=16;o;o>>=1) s+=__shfl_xor_sync(~0u,s,o);
    float inv=1.f/s;
    v0.x*=inv; v0.y*=inv; v0.z*=inv; v0.w*=inv;
    v1.x*=inv; v1.y*=inv; v1.z*=inv; v1.w*=inv;
    *(float4*)(p+lane*8)=v0;
    *(float4*)(p+lane*8+4)=v1;
}

__global__ void scal_reset_kernel(){ g_scal[0]=0.f; g_scal[1]=0.f; }

__global__ void pinv_sums_kernel(){
    int bh=blockIdx.x, t=threadIdx.x;
    const float* A=g_a2+((size_t)bh<<16);
    float rs=0, cs=0;
    const float4* Ar=(const float4*)(A+(size_t)t*ML);
    #pragma unroll
    for(int j=0;j<64;j++){ float4 v=Ar[j]; rs+=fabsf(v.x)+fabsf(v.y)+fabsf(v.z)+fabsf(v.w); }
    for(int j=0;j<ML;j++) cs+=fabsf(A[(size_t)j*ML+t]);
    #pragma unroll
    for(int o=16;o;o>>=1){ rs=fmaxf(rs,__shfl_xor_sync(~0u,rs,o)); cs=fmaxf(cs,__shfl_xor_sync(~0u,cs,o)); }
    __shared__ float r1[8], r2[8];
    if((t&31)==0){ r1[t>>5]=rs; r2[t>>5]=cs; }
    __syncthreads();
    if(t==0){
        float m1=r1[0], m2=r2[0];
        #pragma unroll
        for(int k=1;k<8;k++){ m1=fmaxf(m1,r1[k]); m2=fmaxf(m2,r2[k]); }
        atomicMax((int*)&g_scal[0], __float_as_int(m1));
        atomicMax((int*)&g_scal[1], __float_as_int(m2));
    }
}

__global__ void zinit_kernel(){
    int e=blockIdx.x*256+threadIdx.x;
    float inv=1.f/(g_scal[0]*g_scal[1]);
    int bh=e>>16, r=(e>>8)&255, c=e&255;
    g_z0[e]=g_a2[(bh<<16)+(c<<8)+r]*inv;
}

__global__ void __launch_bounds__(128) mm256_kernel(
        const float* __restrict__ Ag, const float* __restrict__ Bg,
        float* __restrict__ Cg, float cdiag, float alpha){
    int bh=blockIdx.x;
    const float* A=Ag+((size_t)bh<<16);
    const float* B=Bg+((size_t)bh<<16);
    float* C=Cg+((size_t)bh<<16);
    int bm=blockIdx.y*64, bn=blockIdx.z*64;
    __shared__ float As[32][65], Bs[32][65];
    int t=threadIdx.x, tx=t&15, ty=t>>4;
    float acc[8][4]={};
    for(int k0=0;k0<256;k0+=32){
        #pragma unroll
        for(int i=0;i<4;i++){
            int j=t+(i<<7); int r=j>>3, kq=j&7;
            float4 v=*(const float4*)(A+(size_t)(bm+r)*256+k0+(kq<<2));
            As[(kq<<2)+0][r]=v.x; As[(kq<<2)+1][r]=v.y;
            As[(kq<<2)+2][r]=v.z; As[(kq<<2)+3][r]=v.w;
        }
        #pragma unroll
        for(int i=0;i<16;i++){
            int j=t+(i<<7); int kk=j>>6, c=j&63;
            int gk=k0+kk, gc=bn+c;
            float bv=B[(size_t)gk*256+gc];
            Bs[kk][c]=(gk==gc)?(cdiag-bv):(-bv);
        }
        __syncthreads();
        #pragma unroll
        for(int kk=0;kk<32;kk++){
            float a[8], b[4];
            #pragma unroll
            for(int i=0;i<8;i++) a[i]=As[kk][ty*8+i];
            #pragma unroll
            for(int j=0;j<4;j++) b[j]=Bs[kk][tx+(j<<4)];
            #pragma unroll
            for(int i=0;i<8;i++)
                #pragma unroll
                for(int j=0;j<4;j++) acc[i][j]+=a[i]*b[j];
        }
        __syncthreads();
    }
    #pragma unroll
    for(int i=0;i<8;i++)
        #pragma unroll
        for(int j=0;j<4;j++)
            C[(size_t)(bm+ty*8+i)*256+bn+tx+(j<<4)]=alpha*acc[i][j];
}

__global__ void softmax3_kernel(){
    int row=blockIdx.x, t=threadIdx.x;
    float* p=g_sim3+(size_t)row*NTOK;
    float v[32], mx=-3.0e38f;
    #pragma unroll
    for(int i=0;i<32;i++){ v[i]=p[t+(i<<8)]; mx=fmaxf(mx,v[i]); }
    __shared__ float red[8];
    #pragma unroll
    for(int o=16;o;o>>=1) mx=fmaxf(mx,__shfl_xor_sync(~0u,mx,o));
    if((t&31)==0) red[t>>5]=mx;
    __syncthreads();
    mx=red[0];
    #pragma unroll
    for(int k=1;k<8;k++) mx=fmaxf(mx,red[k]);
    float s=0;
    #pragma unroll
    for(int i=0;i<32;i++){ v[i]=__expf(v[i]-mx); s+=v[i]; }
    #pragma unroll
    for(int o=16;o;o>>=1) s+=__shfl_xor_sync(~0u,s,o);
    __syncthreads();
    if((t&31)==0) red[t>>5]=s;
    __syncthreads();
    s=0;
    #pragma unroll
    for(int k=0;k<8;k++) s+=red[k];
    float inv=1.f/s;
    #pragma unroll
    for(int i=0;i<32;i++) p[t+(i<<8)]=v[i]*inv;
}

__global__ void a3v_kernel(){
    __shared__ float As[32][129], Bs[32][65];
    int ksp=blockIdx.x, bm=blockIdx.y*128, bh=blockIdx.z;
    int t=threadIdx.x, tx=t&15, ty=t>>4;
    float acc[8][4]={};
    const float* Ap=g_sim3+(size_t)(bh*ML)*NTOK;
    const float* Vp=g_v+(size_t)bh*NTOK*DH;
    int kbeg=ksp*1024;
    for(int k0=kbeg;k0<kbeg+1024;k0+=32){
        loadA_kmajor(As, Ap, NTOK, bm, k0, t);
        loadB_kn64(Bs, Vp, DH, 0, k0, t);
        __syncthreads();
        fma64(As,Bs,acc,tx,ty);
        __syncthreads();
    }
    #pragma unroll
    for(int i=0;i<8;i++)
        #pragma unroll
        for(int j=0;j<4;j++)
            g_a3vp[(size_t)(ksp*BHN+bh)*ML*DH+(bm+ty*8+i)*DH+tx+(j<<4)]=acc[i][j];
}

__global__ void a3v_reduce_kernel(){
    int e=blockIdx.x*256+threadIdx.x;
    float s=0;
    #pragma unroll
    for(int k=0;k<8;k++) s+=g_a3vp[(size_t)k*BHN*ML*DH+e];
    g_a3v[e]=s;
}

__global__ void z2_kernel(){
    __shared__ float As[32][129], Bs[32][65];
    int bm=blockIdx.x*128, bh=blockIdx.y;
    const float* A=g_z0+((size_t)bh<<16);
    const float* Bp=g_a3v+(size_t)bh*ML*DH;
    int t=threadIdx.x, tx=t&15, ty=t>>4;
    float acc[8][4]={};
    for(int k0=0;k0<256;k0+=32){
        loadA_kmajor(As, A, ML, bm, k0, t);
        loadB_kn64(Bs, Bp, DH, 0, k0, t);
        __syncthreads();
        fma64(As,Bs,acc,tx,ty);
        __syncthreads();
    }
    #pragma unroll
    for(int i=0;i<8;i++)
        #pragma unroll
        for(int j=0;j<4;j++)
            g_Z2[(size_t)bh*ML*DH+(bm+ty*8+i)*DH+tx+(j<<4)]=acc[i][j];
}

__global__ void conv_kernel(const float* __restrict__ cw){
    int idx=blockIdx.x*256+threadIdx.x;
    int d=idx&63, n=(idx>>6)&8191, bh=idx>>19;
    int h=bh&7;
    const float* vp=g_v+(size_t)bh*NTOK*DH+d;
    float s=0;
    #pragma unroll
    for(int kk=0;kk<33;kk++){
        int j=n+kk-16;
        if(j>=0 && j<NTOK) s+=cw[h*33+kk]*vp[(size_t)j*DH];
    }
    g_attn[((size_t)((bh>>3)*NTOK+n))*DIMX+h*64+d]=s;
}

__global__ void a1z2_kernel(){
    __shared__ float As[32][129], Bs[32][65];
    int bm=blockIdx.x*128, bh=blockIdx.y;
    const float* A=g_sim3+(size_t)bh*NTOK*ML;
    const float* Bp=g_Z2+(size_t)bh*ML*DH;
    int t=threadIdx.x, tx=t&15, ty=t>>4;
    float acc[8][4]={};
    for(int k0=0;k0<256;k0+=32){
        loadA_kmajor(As, A, ML, bm, k0, t);
        loadB_kn64(Bs, Bp, DH, 0, k0, t);
        __syncthreads();
        fma64(As,Bs,acc,tx,ty);
        __syncthreads();
    }
    int b=bh>>3, h=bh&7;
    #pragma unroll
    for(int i=0;i<8;i++){
        size_t base=((size_t)(b*NTOK+bm+ty*8+i))*DIMX+h*64;
        #pragma unroll
        for(int j=0;j<4;j++)
            g_attn[base+tx+(j<<4)]+=acc[i][j];
    }
}

extern "C" void kernel_launch(void* const* d_in, const int* in_sizes, int n_in,
                              void* d_out, int out_size){
    const float* x    = (const float*)d_in[0];
    const float* ln_w = (const float*)d_in[2];
    const float* ln_b = (const float*)d_in[3];
    const float* wqkv = (const float*)d_in[4];
    const float* wout = (const float*)d_in[5];
    const float* bout = (const float*)d_in[6];
    const float* cw   = (const float*)d_in[7];
    float* out = (float*)d_out;

    cudaFuncSetAttribute(bf_gemm, cudaFuncAttributeMaxDynamicSharedMemorySize, 65536);

    float *z0,*z1,*a2p,*xz,*t1,*t2,*qlp,*klp,*qp,*kp,*sim3p;
    __nv_bfloat16 *bhi,*blo,*wqhi,*wqlo,*wohi,*wolo;
    cudaGetSymbolAddress((void**)&z0, g_z0);
    cudaGetSymbolAddress((void**)&z1, g_z1);
    cudaGetSymbolAddress((void**)&a2p, g_a2);
    cudaGetSymbolAddress((void**)&xz, g_xz);
    cudaGetSymbolAddress((void**)&t1, g_t1);
    cudaGetSymbolAddress((void**)&t2, g_t2);
    cudaGetSymbolAddress((void**)&qlp, g_ql);
    cudaGetSymbolAddress((void**)&klp, g_kl);
    cudaGetSymbolAddress((void**)&qp, g_q);
    cudaGetSymbolAddress((void**)&kp, g_k);
    cudaGetSymbolAddress((void**)&sim3p, g_sim3);
    cudaGetSymbolAddress((void**)&bhi, g_bhi);
    cudaGetSymbolAddress((void**)&blo, g_blo);
    cudaGetSymbolAddress((void**)&wqhi, g_wqhi);
    cudaGetSymbolAddress((void**)&wqlo, g_wqlo);
    cudaGetSymbolAddress((void**)&wohi, g_wohi);
    cudaGetSymbolAddress((void**)&wolo, g_wolo);

    wtrans_kernel<<<dim3(48,16), 256>>>(wqkv, wqhi, wqlo, 512, 1536);
    wtrans_kernel<<<dim3(16,16), 256>>>(wout, wohi, wolo, 512, 512);

    ln_kernel<<<BB*NTOK, 256>>>(x, ln_w, ln_b);

    bf_gemm<<<dim3(12,128), 128, 65536>>>(bhi, blo, wqhi, wqlo, 0, nullptr, nullptr, nullptr);

    landmark_kernel<<<BHN*ML, 64>>>();

    sim_kernel<<<dim3(2,2,BHN), 256>>>(qlp, klp, a2p,
        (size_t)ML*DH, (size_t)ML*DH, (size_t)ML*ML, ML);
    softmax256_kernel<<<BHN*ML/8, 256>>>(a2p);

    scal_reset_kernel<<<1,1>>>();
    pinv_sums_kernel<<<BHN, 256>>>();
    zinit_kernel<<<4096, 256>>>();

    float* zc=z0; float* za=z1;
    for(int it=0; it<6; it++){
        mm256_kernel<<<dim3(BHN,4,4),128>>>(a2p, zc, xz, 0.f, -1.f);
        mm256_kernel<<<dim3(BHN,4,4),128>>>(xz, xz, t1, 7.f, 1.f);
        mm256_kernel<<<dim3(BHN,4,4),128>>>(xz, t1, t2, 15.f, 1.f);
        mm256_kernel<<<dim3(BHN,4,4),128>>>(zc, t2, za, 13.f, 0.25f);
        float* tmp=zc; zc=za; za=tmp;
    }

    sim_kernel<<<dim3(64,2,BHN), 256>>>(qlp, kp, sim3p,
        (size_t)ML*DH, (size_t)NTOK*DH, (size_t)ML*NTOK, NTOK);
    softmax3_kernel<<<BHN*ML, 256>>>();
    a3v_kernel<<<dim3(8,2,BHN), 256>>>();
    a3v_reduce_kernel<<<1024, 256>>>();
    z2_kernel<<<dim3(2,BHN), 256>>>();
    conv_kernel<<<32768, 256>>>(cw);

    sim_kernel<<<dim3(2,64,BHN), 256>>>(qp, klp, sim3p,
        (size_t)NTOK*DH, (size_t)ML*DH, (size_t)NTOK*ML, ML);
    softmax256_kernel<<<BHN*NTOK/8, 256>>>(sim3p);
    a1z2_kernel<<<dim3(64,BHN), 256>>>();

    a2bf_kernel<<<8192, 256>>>();
    bf_gemm<<<dim3(4,128), 128, 65536>>>(bhi, blo, wohi, wolo, 1, x, bout, out);
}

// round 16
// speedup vs baseline: 1.1537x; 1.0114x over previous
#include <cuda_runtime.h>
#include <cuda_bf16.h>
#include <math.h>
#include <stdint.h>

#define BB 2
#define NTOK 8192
#define DIMX 512
#define NH 8
#define DH 64
#define ML 256
#define BHN 16

__device__ float g_q [BHN*NTOK*DH];
__device__ float g_k [BHN*NTOK*DH];
__device__ float g_v [BHN*NTOK*DH];
__device__ float g_ql[BHN*ML*DH];
__device__ float g_kl[BHN*ML*DH];
__device__ float g_a2[BHN*ML*ML];
__device__ float g_z0[BHN*ML*ML];
__device__ float g_z1[BHN*ML*ML];
__device__ float g_sim3[(size_t)BHN*ML*NTOK];
__device__ float g_a3vp[8*BHN*ML*DH];
__device__ float g_a3v [BHN*ML*DH];
__device__ float g_Z2  [BHN*ML*DH];
__device__ float g_attn[BB*NTOK*DIMX];
__device__ float g_scal[2];
__device__ __nv_bfloat16 g_bhi[BB*NTOK*DIMX];
__device__ __nv_bfloat16 g_blo[BB*NTOK*DIMX];
__device__ __nv_bfloat16 g_wqhi[1536*512];
__device__ __nv_bfloat16 g_wqlo[1536*512];
__device__ __nv_bfloat16 g_wohi[512*512];
__device__ __nv_bfloat16 g_wolo[512*512];
// pinv chain bf16 operands
__device__ __nv_bfloat16 g_a2hi[BHN*ML*ML], g_a2lo[BHN*ML*ML];
__device__ __nv_bfloat16 g_z0hi[BHN*ML*ML], g_z0lo[BHN*ML*ML];
__device__ __nv_bfloat16 g_z1hi[BHN*ML*ML], g_z1lo[BHN*ML*ML];
__device__ __nv_bfloat16 g_xzhi[BHN*ML*ML], g_xzlo[BHN*ML*ML];
__device__ __nv_bfloat16 g_t1hi[BHN*ML*ML], g_t1lo[BHN*ML*ML];
__device__ __nv_bfloat16 g_t2hi[BHN*ML*ML], g_t2lo[BHN*ML*ML];

// ================= bf16 mma.sync + ldmatrix + cp.async =================
__device__ __forceinline__ void mma16816(float* c, const uint32_t* a, const uint32_t* b){
    asm volatile("mma.sync.aligned.m16n8k16.row.col.f32.bf16.bf16.f32 "
        "{%0,%1,%2,%3},{%4,%5,%6,%7},{%8,%9},{%0,%1,%2,%3};"
        : "+f"(c[0]),"+f"(c[1]),"+f"(c[2]),"+f"(c[3])
        : "r"(a[0]),"r"(a[1]),"r"(a[2]),"r"(a[3]),"r"(b[0]),"r"(b[1]));
}
__device__ __forceinline__ uint32_t cvta_s(const void* p){
    uint32_t a;
    asm("{ .reg .u64 t; cvta.to.shared.u64 t, %1; cvt.u32.u64 %0, t; }" : "=r"(a) : "l"(p));
    return a;
}
#define LDSM4(r, a) \
    asm volatile("ldmatrix.sync.aligned.m8n8.x4.shared.b16 {%0,%1,%2,%3}, [%4];" \
        : "=r"((r)[0]),"=r"((r)[1]),"=r"((r)[2]),"=r"((r)[3]) : "r"(a))
#define LDSM4T(r, a) \
    asm volatile("ldmatrix.sync.aligned.m8n8.x4.trans.shared.b16 {%0,%1,%2,%3}, [%4];" \
        : "=r"((r)[0]),"=r"((r)[1]),"=r"((r)[2]),"=r"((r)[3]) : "r"(a))
#define SWZ(o) ((o) ^ (((o)>>3)&0x70))
#define CPA16(dst, src) \
    asm volatile("cp.async.cg.shared.global [%0], [%1], 16;" :: "r"(dst), "l"(src))
#define CPA_COMMIT() asm volatile("cp.async.commit_group;")
#define CPA_WAIT1() asm volatile("cp.async.wait_group 1;")
#define CPA_WAIT0() asm volatile("cp.async.wait_group 0;")

__device__ __forceinline__ void bf_stage_issue(
    uint32_t sAb, uint32_t sBb,
    const __nv_bfloat16* __restrict__ Asrc, const __nv_bfloat16* __restrict__ Bsrc,
    int bm, int bn, int kb, int t)
{
    #pragma unroll
    for(int i=0;i<8;i++){
        int j=t+(i<<7); int row=j>>3, cg=j&7;
        CPA16(sAb+SWZ(row*128+(cg<<4)), Asrc+(size_t)(bm+row)*512+kb+(cg<<3));
    }
    #pragma unroll
    for(int i=0;i<8;i++){
        int j=t+(i<<7); int row=j>>3, cg=j&7;
        CPA16(sBb+SWZ(row*128+(cg<<4)), Bsrc+(size_t)(bn+row)*512+kb+(cg<<3));
    }
    CPA_COMMIT();
}

// bf16-split GEMM: C[128x128] = A @ B^T over Keff = 3*512, double-buffered cp.async.
__global__ void __launch_bounds__(128) bf_gemm(
    const __nv_bfloat16* __restrict__ Ahi, const __nv_bfloat16* __restrict__ Alo,
    const __nv_bfloat16* __restrict__ BhiT, const __nv_bfloat16* __restrict__ BloT,
    int mode, const float* __restrict__ xres, const float* __restrict__ bias,
    float* __restrict__ outp)
{
    extern __shared__ __align__(1024) unsigned char dyns[];
    int t=threadIdx.x, lane=t&31, wid=t>>5;
    int g=lane>>2, tig=lane&3;
    int wm=wid&1, wn=wid>>1;
    int bn=blockIdx.x*128, bm=blockIdx.y*128;
    uint32_t base=cvta_s(dyns);
    uint32_t sA32[2]={base, base+32768u};
    uint32_t sB32[2]={base+16384u, base+49152u};
    int lrow=lane&15, lkh=(lane>>4)<<4;
    float acc[4][8][4];
    #pragma unroll
    for(int a=0;a<4;a++)
        #pragma unroll
        for(int b=0;b<8;b++)
            #pragma unroll
            for(int c=0;c<4;c++) acc[a][b][c]=0.f;

    bf_stage_issue(sA32[0], sB32[0], Ahi, BhiT, bm, bn, 0, t);
    for(int blk=0;blk<24;blk++){
        if(blk+1<24){
            int nb=blk+1;
            int seg=nb>>3, kb=(nb&7)<<6;
            const __nv_bfloat16* Asrc=(seg<2)?Ahi:Alo;
            const __nv_bfloat16* Bsrc=(seg==1)?BloT:BhiT;
            bf_stage_issue(sA32[nb&1], sB32[nb&1], Asrc, Bsrc, bm, bn, kb, t);
            CPA_WAIT1();
        } else {
            CPA_WAIT0();
        }
        __syncthreads();
        int buf=blk&1;
        #pragma unroll
        for(int kc=0;kc<4;kc++){
            int kboff=kc*32+lkh;
            uint32_t af[4][4], bfr[8][2];
            #pragma unroll
            for(int mt=0;mt<4;mt++){
                uint32_t addr=sA32[buf]+SWZ((wm*64+mt*16+lrow)*128+kboff);
                LDSM4(af[mt], addr);
            }
            #pragma unroll
            for(int p=0;p<4;p++){
                uint32_t r4[4];
                uint32_t addr=sB32[buf]+SWZ((wn*64+p*16+lrow)*128+kboff);
                LDSM4(r4, addr);
                bfr[2*p][0]=r4[0]; bfr[2*p+1][0]=r4[1];
                bfr[2*p][1]=r4[2]; bfr[2*p+1][1]=r4[3];
            }
            #pragma unroll
            for(int mt=0;mt<4;mt++)
                #pragma unroll
                for(int nt=0;nt<8;nt++)
                    mma16816(acc[mt][nt], af[mt], bfr[nt]);
        }
        __syncthreads();
    }

    #pragma unroll
    for(int mt=0;mt<4;mt++)
        #pragma unroll
        for(int nt=0;nt<8;nt++)
            #pragma unroll
            for(int ci=0;ci<4;ci++){
                int row=bm+wm*64+mt*16+g+((ci>>1)<<3);
                int col=bn+wn*64+nt*8+(tig<<1)+(ci&1);
                float val=acc[mt][nt][ci];
                if(mode==0){
                    int b_=row>>13, n=row&8191;
                    int s=col>>9, inner=col&511, h=inner>>6, d=inner&63;
                    size_t o=((size_t)((b_*NH+h)*NTOK+n))*DH+d;
                    if(s==0) g_q[o]=val*0.125f;
                    else if(s==1) g_k[o]=val;
                    else g_v[o]=val;
                } else {
                    size_t o=(size_t)row*DIMX+col;
                    outp[o]=xres[o]+bias[col]+val;
                }
            }
}

// ---- bf16-split batched 256x256x256: C = ca*A + cp*(A@B), B row-major [k][n] ----
__global__ void __launch_bounds__(128) bmm256(
    const __nv_bfloat16* __restrict__ Ahi, const __nv_bfloat16* __restrict__ Alo,
    const __nv_bfloat16* __restrict__ Bhi, const __nv_bfloat16* __restrict__ Blo,
    float ca, float cp,
    __nv_bfloat16* __restrict__ Chi, __nv_bfloat16* __restrict__ Clo,
    float* __restrict__ Cf32)
{
    __shared__ __align__(1024) unsigned char sA[16384];
    __shared__ __align__(1024) unsigned char sB[8192];
    int bh=blockIdx.z;
    size_t boff=(size_t)bh<<16;
    int t=threadIdx.x, lane=t&31, wid=t>>5;
    int g=lane>>2, tig=lane&3;
    int wm=wid&1, wn=wid>>1;
    int bn=blockIdx.x*64, bm=blockIdx.y*128;
    uint32_t sA32=cvta_s(sA), sB32=cvta_s(sB);
    int lrow=lane&15, lkh=(lane>>4)<<4;
    float acc[4][4][4];
    #pragma unroll
    for(int a=0;a<4;a++)
        #pragma unroll
        for(int b=0;b<4;b++)
            #pragma unroll
            for(int c=0;c<4;c++) acc[a][b][c]=0.f;

    for(int pass=0;pass<3;pass++){
        const __nv_bfloat16* As=((pass<2)?Ahi:Alo)+boff;
        const __nv_bfloat16* Bs=((pass==1)?Blo:Bhi)+boff;
        for(int k0=0;k0<256;k0+=64){
            #pragma unroll
            for(int i=0;i<8;i++){
                int j=t+(i<<7); int row=j>>3, cg=j&7;
                uint4 v=*(const uint4*)(As+(size_t)(bm+row)*256+k0+(cg<<3));
                *(uint4*)(sA+SWZ(row*128+(cg<<4)))=v;
            }
            #pragma unroll
            for(int i=0;i<4;i++){
                int j=t+(i<<7); int row=j>>3, cg=j&7;
                uint4 v=*(const uint4*)(Bs+(size_t)(k0+row)*256+bn+(cg<<3));
                *(uint4*)(sB+SWZ(row*128+(cg<<4)))=v;
            }
            __syncthreads();
            #pragma unroll
            for(int kc=0;kc<4;kc++){
                uint32_t af[4][4], bfr[4][2];
                #pragma unroll
                for(int mt=0;mt<4;mt++){
                    uint32_t addr=sA32+SWZ((wm*64+mt*16+lrow)*128+kc*32+lkh);
                    LDSM4(af[mt], addr);
                }
                #pragma unroll
                for(int p=0;p<2;p++){
                    uint32_t r4[4];
                    uint32_t addr=sB32+SWZ((kc*16+lrow)*128+(wn*32+p*16+((lane>>4)<<3))*2);
                    LDSM4T(r4, addr);
                    bfr[2*p][0]=r4[0]; bfr[2*p][1]=r4[1];
                    bfr[2*p+1][0]=r4[2]; bfr[2*p+1][1]=r4[3];
                }
                #pragma unroll
                for(int mt=0;mt<4;mt++)
                    #pragma unroll
                    for(int nt=0;nt<4;nt++)
                        mma16816(acc[mt][nt], af[mt], bfr[nt]);
            }
            __syncthreads();
        }
    }

    #pragma unroll
    for(int mt=0;mt<4;mt++)
        #pragma unroll
        for(int nt=0;nt<4;nt++)
            #pragma unroll
            for(int ci=0;ci<4;ci++){
                int row=bm+wm*64+mt*16+g+((ci>>1)<<3);
                int col=bn+wn*32+nt*8+(tig<<1)+(ci&1);
                size_t o=boff+(size_t)row*256+col;
                float aelem=__bfloat162float(Ahi[o])+__bfloat162float(Alo[o]);
                float val=ca*aelem+cp*acc[mt][nt][ci];
                __nv_bfloat16 h=__float2bfloat16(val);
                Chi[o]=h;
                Clo[o]=__float2bfloat16(val-__bfloat162float(h));
                if(Cf32) Cf32[o]=val;
            }
}

// ---- weight transpose + bf16 hi/lo split ----
__global__ void wtrans_kernel(const float* __restrict__ W,
                              __nv_bfloat16* __restrict__ BhiT, __nv_bfloat16* __restrict__ BloT,
                              int K, int N){
    __shared__ float tile[32][33];
    int k0=blockIdx.y*32, n0=blockIdx.x*32;
    int tx=threadIdx.x&31, ty=threadIdx.x>>5;
    #pragma unroll
    for(int i=0;i<32;i+=8) tile[ty+i][tx]=W[(size_t)(k0+ty+i)*N+n0+tx];
    __syncthreads();
    #pragma unroll
    for(int i=0;i<32;i+=8){
        int n=n0+ty+i, k=k0+tx;
        float v=tile[tx][ty+i];
        __nv_bfloat16 h=__float2bfloat16(v);
        BhiT[(size_t)n*K+k]=h;
        BloT[(size_t)n*K+k]=__float2bfloat16(v-__bfloat162float(h));
    }
}

__global__ void a2bf_kernel(){
    size_t i4=((size_t)blockIdx.x*256+threadIdx.x)*4;
    float4 v=*(const float4*)(g_attn+i4);
    float xs[4]={v.x,v.y,v.z,v.w};
    #pragma unroll
    for(int j=0;j<4;j++){
        __nv_bfloat16 h=__float2bfloat16(xs[j]);
        g_bhi[i4+j]=h;
        g_blo[i4+j]=__float2bfloat16(xs[j]-__bfloat162float(h));
    }
}

__global__ void ln_kernel(const float* __restrict__ x, const float* __restrict__ w,
                          const float* __restrict__ bp){
    int row=blockIdx.x, t=threadIdx.x;
    const float* xr=x+(size_t)row*DIMX;
    float v0=xr[t], v1=xr[t+256];
    float s=v0+v1, sq=v0*v0+v1*v1;
    __shared__ float r1[8], r2[8];
    #pragma unroll
    for(int o=16;o;o>>=1){ s+=__shfl_xor_sync(~0u,s,o); sq+=__shfl_xor_sync(~0u,sq,o); }
    if((t&31)==0){ r1[t>>5]=s; r2[t>>5]=sq; }
    __syncthreads();
    float ss=0, qq=0;
    #pragma unroll
    for(int i=0;i<8;i++){ ss+=r1[i]; qq+=r2[i]; }
    float mean=ss*(1.f/512.f);
    float rstd=rsqrtf(qq*(1.f/512.f)-mean*mean+1e-5f);
    float y0=(v0-mean)*rstd*w[t]+bp[t];
    float y1=(v1-mean)*rstd*w[t+256]+bp[t+256];
    __nv_bfloat16 h0=__float2bfloat16(y0), h1=__float2bfloat16(y1);
    size_t b=(size_t)row*DIMX;
    g_bhi[b+t]=h0;      g_blo[b+t]=__float2bfloat16(y0-__bfloat162float(h0));
    g_bhi[b+t+256]=h1;  g_blo[b+t+256]=__float2bfloat16(y1-__bfloat162float(h1));
}

// ================= fp32 SIMT cores =================
__device__ __forceinline__ void loadA_kmajor(float (*As)[129], const float* __restrict__ Ag,
                                             int lda, int bm, int k0, int t){
    #pragma unroll
    for(int i=0;i<4;i++){
        int q=t+(i<<8); int r=q>>3; int kq=q&7;
        float4 v=*(const float4*)(Ag+(size_t)(bm+r)*lda+k0+(kq<<2));
        As[(kq<<2)+0][r]=v.x; As[(kq<<2)+1][r]=v.y;
        As[(kq<<2)+2][r]=v.z; As[(kq<<2)+3][r]=v.w;
    }
}
__device__ __forceinline__ void loadB_kn64(float (*Bs)[65], const float* __restrict__ Bg,
                                           int ldb, int bn, int k0, int t){
    #pragma unroll
    for(int i=0;i<2;i++){
        int q=t+(i<<8); int kk=q>>4; int cq=q&15;
        float4 v=*(const float4*)(Bg+(size_t)(k0+kk)*ldb+bn+(cq<<2));
        Bs[kk][(cq<<2)+0]=v.x; Bs[kk][(cq<<2)+1]=v.y;
        Bs[kk][(cq<<2)+2]=v.z; Bs[kk][(cq<<2)+3]=v.w;
    }
}
__device__ __forceinline__ void fma128(const float (*As)[129], const float (*Bs)[129],
                                       float acc[8][8], int tx, int ty){
    #pragma unroll
    for(int kk=0;kk<32;kk++){
        float a[8], b[8];
        #pragma unroll
        for(int i=0;i<8;i++) a[i]=As[kk][ty*8+i];
        #pragma unroll
        for(int j=0;j<8;j++) b[j]=Bs[kk][tx+(j<<4)];
        #pragma unroll
        for(int i=0;i<8;i++)
            #pragma unroll
            for(int j=0;j<8;j++) acc[i][j]+=a[i]*b[j];
    }
}
__device__ __forceinline__ void fma64(const float (*As)[129], const float (*Bs)[65],
                                      float acc[8][4], int tx, int ty){
    #pragma unroll
    for(int kk=0;kk<32;kk++){
        float a[8], b[4];
        #pragma unroll
        for(int i=0;i<8;i++) a[i]=As[kk][ty*8+i];
        #pragma unroll
        for(int j=0;j<4;j++) b[j]=Bs[kk][tx+(j<<4)];
        #pragma unroll
        for(int i=0;i<8;i++)
            #pragma unroll
            for(int j=0;j<4;j++) acc[i][j]+=a[i]*b[j];
    }
}

__global__ void landmark_kernel(){
    int blk=blockIdx.x, bh=blk>>8, m=blk&255, d=threadIdx.x;
    const float* qp=g_q+((size_t)(bh*NTOK+m*32))*DH+d;
    const float* kp=g_k+((size_t)(bh*NTOK+m*32))*DH+d;
    float sq=0,sk=0;
    #pragma unroll
    for(int j=0;j<32;j++){ sq+=qp[(size_t)j*DH]; sk+=kp[(size_t)j*DH]; }
    g_ql[(bh*ML+m)*DH+d]=sq*(1.f/32.f);
    g_kl[(bh*ML+m)*DH+d]=sk*(1.f/32.f);
}

__global__ void sim_kernel(const float* __restrict__ Abase, const float* __restrict__ Bbase,
                           float* __restrict__ Cbase, size_t aBH, size_t bBH, size_t cBH, int ldC){
    __shared__ float As[32][129], Bs[32][129];
    int t=threadIdx.x, tx=t&15, ty=t>>4;
    int bh=blockIdx.z;
    int bn=blockIdx.x*128, bm=blockIdx.y*128;
    const float* A=Abase+(size_t)bh*aBH;
    const float* B=Bbase+(size_t)bh*bBH;
    float* C=Cbase+(size_t)bh*cBH;
    float acc[8][8]={};
    for(int k0=0;k0<64;k0+=32){
        loadA_kmajor(As, A, DH, bm, k0, t);
        loadA_kmajor(Bs, B, DH, bn, k0, t);
        __syncthreads();
        fma128(As,Bs,acc,tx,ty);
        __syncthreads();
    }
    #pragma unroll
    for(int i=0;i<8;i++)
        #pragma unroll
        for(int j=0;j<8;j++)
            C[(size_t)(bm+ty*8+i)*ldC+bn+tx+(j<<4)]=acc[i][j];
}

__global__ void softmax256_kernel(float* __restrict__ base,
                                  __nv_bfloat16* __restrict__ ohi,
                                  __nv_bfloat16* __restrict__ olo){
    int w=threadIdx.x>>5, lane=threadIdx.x&31;
    size_t row=(size_t)blockIdx.x*8+w;
    float* p=base+row*ML;
    float4 v0=*(float4*)(p+lane*8);
    float4 v1=*(float4*)(p+lane*8+4);
    float mx=fmaxf(fmaxf(fmaxf(v0.x,v0.y),fmaxf(v0.z,v0.w)),
                   fmaxf(fmaxf(v1.x,v1.y),fmaxf(v1.z,v1.w)));
    #pragma unroll
    for(int o=16;o;o>>=1) mx=fmaxf(mx,__shfl_xor_sync(~0u,mx,o));
    v0.x=__expf(v0.x-mx); v0.y=__expf(v0.y-mx); v0.z=__expf(v0.z-mx); v0.w=__expf(v0.w-mx);
    v1.x=__expf(v1.x-mx); v1.y=__expf(v1.y-mx); v1.z=__expf(v1.z-mx); v1.w=__expf(v1.w-mx);
    float s=v0.x+v0.y+v0.z+v0.w+v1.x+v1.y+v1.z+v1.w;
    #pragma unroll
    for(int o=16;o;o>>=1) s+=__shfl_xor_sync(~0u,s,o);
    float inv=1.f/s;
    v0.x*=inv; v0.y*=inv; v0.z*=inv; v0.w*=inv;
    v1.x*=inv; v1.y*=inv; v1.z*=inv; v1.w*=inv;
    *(float4*)(p+lane*8)=v0;
    *(float4*)(p+lane*8+4)=v1;
    if(ohi){
        float xs[8]={v0.x,v0.y,v0.z,v0.w,v1.x,v1.y,v1.z,v1.w};
        #pragma unroll
        for(int i=0;i<8;i++){
            __nv_bfloat16 h=__float2bfloat16(xs[i]);
            ohi[row*ML+lane*8+i]=h;
            olo[row*ML+lane*8+i]=__float2bfloat16(xs[i]-__bfloat162float(h));
        }
    }
}

__global__ void scal_reset_kernel(){ g_scal[0]=0.f; g_scal[1]=0.f; }

__global__ void pinv_sums_kernel(){
    int bh=blockIdx.x, t=threadIdx.x;
    const float* A=g_a2+((size_t)bh<<16);
    float rs=0, cs=0;
    const float4* Ar=(const float4*)(A+(size_t)t*ML);
    #pragma unroll
    for(int j=0;j<64;j++){ float4 v=Ar[j]; rs+=fabsf(v.x)+fabsf(v.y)+fabsf(v.z)+fabsf(v.w); }
    for(int j=0;j<ML;j++) cs+=fabsf(A[(size_t)j*ML+t]);
    #pragma unroll
    for(int o=16;o;o>>=1){ rs=fmaxf(rs,__shfl_xor_sync(~0u,rs,o)); cs=fmaxf(cs,__shfl_xor_sync(~0u,cs,o)); }
    __shared__ float r1[8], r2[8];
    if((t&31)==0){ r1[t>>5]=rs; r2[t>>5]=cs; }
    __syncthreads();
    if(t==0){
        float m1=r1[0], m2=r2[0];
        #pragma unroll
        for(int k=1;k<8;k++){ m1=fmaxf(m1,r1[k]); m2=fmaxf(m2,r2[k]); }
        atomicMax((int*)&g_scal[0], __float_as_int(m1));
        atomicMax((int*)&g_scal[1], __float_as_int(m2));
    }
}

__global__ void zinit_kernel(){
    int e=blockIdx.x*256+threadIdx.x;
    float inv=1.f/(g_scal[0]*g_scal[1]);
    int bh=e>>16, r=(e>>8)&255, c=e&255;
    float v=g_a2[(bh<<16)+(c<<8)+r]*inv;
    g_z0[e]=v;
    __nv_bfloat16 h=__float2bfloat16(v);
    g_z0hi[e]=h;
    g_z0lo[e]=__float2bfloat16(v-__bfloat162float(h));
}

__global__ void softmax3_kernel(){
    int row=blockIdx.x, t=threadIdx.x;
    float* p=g_sim3+(size_t)row*NTOK;
    float v[32], mx=-3.0e38f;
    #pragma unroll
    for(int i=0;i<32;i++){ v[i]=p[t+(i<<8)]; mx=fmaxf(mx,v[i]); }
    __shared__ float red[8];
    #pragma unroll
    for(int o=16;o;o>>=1) mx=fmaxf(mx,__shfl_xor_sync(~0u,mx,o));
    if((t&31)==0) red[t>>5]=mx;
    __syncthreads();
    mx=red[0];
    #pragma unroll
    for(int k=1;k<8;k++) mx=fmaxf(mx,red[k]);
    float s=0;
    #pragma unroll
    for(int i=0;i<32;i++){ v[i]=__expf(v[i]-mx); s+=v[i]; }
    #pragma unroll
    for(int o=16;o;o>>=1) s+=__shfl_xor_sync(~0u,s,o);
    __syncthreads();
    if((t&31)==0) red[t>>5]=s;
    __syncthreads();
    s=0;
    #pragma unroll
    for(int k=0;k<8;k++) s+=red[k];
    float inv=1.f/s;
    #pragma unroll
    for(int i=0;i<32;i++) p[t+(i<<8)]=v[i]*inv;
}

__global__ void a3v_kernel(){
    __shared__ float As[32][129], Bs[32][65];
    int ksp=blockIdx.x, bm=blockIdx.y*128, bh=blockIdx.z;
    int t=threadIdx.x, tx=t&15, ty=t>>4;
    float acc[8][4]={};
    const float* Ap=g_sim3+(size_t)(bh*ML)*NTOK;
    const float* Vp=g_v+(size_t)bh*NTOK*DH;
    int kbeg=ksp*1024;
    for(int k0=kbeg;k0<kbeg+1024;k0+=32){
        loadA_kmajor(As, Ap, NTOK, bm, k0, t);
        loadB_kn64(Bs, Vp, DH, 0, k0, t);
        __syncthreads();
        fma64(As,Bs,acc,tx,ty);
        __syncthreads();
    }
    #pragma unroll
    for(int i=0;i<8;i++)
        #pragma unroll
        for(int j=0;j<4;j++)
            g_a3vp[(size_t)(ksp*BHN+bh)*ML*DH+(bm+ty*8+i)*DH+tx+(j<<4)]=acc[i][j];
}

__global__ void a3v_reduce_kernel(){
    int e=blockIdx.x*256+threadIdx.x;
    float s=0;
    #pragma unroll
    for(int k=0;k<8;k++) s+=g_a3vp[(size_t)k*BHN*ML*DH+e];
    g_a3v[e]=s;
}

__global__ void z2_kernel(){
    __shared__ float As[32][129], Bs[32][65];
    int bm=blockIdx.x*128, bh=blockIdx.y;
    const float* A=g_z0+((size_t)bh<<16);
    const float* Bp=g_a3v+(size_t)bh*ML*DH;
    int t=threadIdx.x, tx=t&15, ty=t>>4;
    float acc[8][4]={};
    for(int k0=0;k0<256;k0+=32){
        loadA_kmajor(As, A, ML, bm, k0, t);
        loadB_kn64(Bs, Bp, DH, 0, k0, t);
        __syncthreads();
        fma64(As,Bs,acc,tx,ty);
        __syncthreads();
    }
    #pragma unroll
    for(int i=0;i<8;i++)
        #pragma unroll
        for(int j=0;j<4;j++)
            g_Z2[(size_t)bh*ML*DH+(bm+ty*8+i)*DH+tx+(j<<4)]=acc[i][j];
}

__global__ void conv_kernel(const float* __restrict__ cw){
    int idx=blockIdx.x*256+threadIdx.x;
    int d=idx&63, n=(idx>>6)&8191, bh=idx>>19;
    int h=bh&7;
    const float* vp=g_v+(size_t)bh*NTOK*DH+d;
    float s=0;
    #pragma unroll
    for(int kk=0;kk<33;kk++){
        int j=n+kk-16;
        if(j>=0 && j<NTOK) s+=cw[h*33+kk]*vp[(size_t)j*DH];
    }
    g_attn[((size_t)((bh>>3)*NTOK+n))*DIMX+h*64+d]=s;
}

__global__ void a1z2_kernel(){
    __shared__ float As[32][129], Bs[32][65];
    int bm=blockIdx.x*128, bh=blockIdx.y;
    const float* A=g_sim3+(size_t)bh*NTOK*ML;
    const float* Bp=g_Z2+(size_t)bh*ML*DH;
    int t=threadIdx.x, tx=t&15, ty=t>>4;
    float acc[8][4]={};
    for(int k0=0;k0<256;k0+=32){
        loadA_kmajor(As, A, ML, bm, k0, t);
        loadB_kn64(Bs, Bp, DH, 0, k0, t);
        __syncthreads();
        fma64(As,Bs,acc,tx,ty);
        __syncthreads();
    }
    int b=bh>>3, h=bh&7;
    #pragma unroll
    for(int i=0;i<8;i++){
        size_t base=((size_t)(b*NTOK+bm+ty*8+i))*DIMX+h*64;
        #pragma unroll
        for(int j=0;j<4;j++)
            g_attn[base+tx+(j<<4)]+=acc[i][j];
    }
}

extern "C" void kernel_launch(void* const* d_in, const int* in_sizes, int n_in,
                              void* d_out, int out_size){
    const float* x    = (const float*)d_in[0];
    const float* ln_w = (const float*)d_in[2];
    const float* ln_b = (const float*)d_in[3];
    const float* wqkv = (const float*)d_in[4];
    const float* wout = (const float*)d_in[5];
    const float* bout = (const float*)d_in[6];
    const float* cw   = (const float*)d_in[7];
    float* out = (float*)d_out;

    cudaFuncSetAttribute(bf_gemm, cudaFuncAttributeMaxDynamicSharedMemorySize, 65536);

    float *z0,*z1,*a2p,*qlp,*klp,*qp,*kp,*sim3p;
    __nv_bfloat16 *bhi,*blo,*wqhi,*wqlo,*wohi,*wolo;
    __nv_bfloat16 *a2h,*a2l,*z0h,*z0l,*z1h,*z1l,*xzh,*xzl,*t1h,*t1l,*t2h,*t2l;
    cudaGetSymbolAddress((void**)&z0, g_z0);
    cudaGetSymbolAddress((void**)&z1, g_z1);
    cudaGetSymbolAddress((void**)&a2p, g_a2);
    cudaGetSymbolAddress((void**)&qlp, g_ql);
    cudaGetSymbolAddress((void**)&klp, g_kl);
    cudaGetSymbolAddress((void**)&qp, g_q);
    cudaGetSymbolAddress((void**)&kp, g_k);
    cudaGetSymbolAddress((void**)&sim3p, g_sim3);
    cudaGetSymbolAddress((void**)&bhi, g_bhi);
    cudaGetSymbolAddress((void**)&blo, g_blo);
    cudaGetSymbolAddress((void**)&wqhi, g_wqhi);
    cudaGetSymbolAddress((void**)&wqlo, g_wqlo);
    cudaGetSymbolAddress((void**)&wohi, g_wohi);
    cudaGetSymbolAddress((void**)&wolo, g_wolo);
    cudaGetSymbolAddress((void**)&a2h, g_a2hi);
    cudaGetSymbolAddress((void**)&a2l, g_a2lo);
    cudaGetSymbolAddress((void**)&z0h, g_z0hi);
    cudaGetSymbolAddress((void**)&z0l, g_z0lo);
    cudaGetSymbolAddress((void**)&z1h, g_z1hi);
    cudaGetSymbolAddress((void**)&z1l, g_z1lo);
    cudaGetSymbolAddress((void**)&xzh, g_xzhi);
    cudaGetSymbolAddress((void**)&xzl, g_xzlo);
    cudaGetSymbolAddress((void**)&t1h, g_t1hi);
    cudaGetSymbolAddress((void**)&t1l, g_t1lo);
    cudaGetSymbolAddress((void**)&t2h, g_t2hi);
    cudaGetSymbolAddress((void**)&t2l, g_t2lo);

    wtrans_kernel<<<dim3(48,16), 256>>>(wqkv, wqhi, wqlo, 512, 1536);
    wtrans_kernel<<<dim3(16,16), 256>>>(wout, wohi, wolo, 512, 512);

    ln_kernel<<<BB*NTOK, 256>>>(x, ln_w, ln_b);
    bf_gemm<<<dim3(12,128), 128, 65536>>>(bhi, blo, wqhi, wqlo, 0, nullptr, nullptr, nullptr);
    landmark_kernel<<<BHN*ML, 64>>>();

    sim_kernel<<<dim3(2,2,BHN), 256>>>(qlp, klp, a2p,
        (size_t)ML*DH, (size_t)ML*DH, (size_t)ML*ML, ML);
    softmax256_kernel<<<BHN*ML/8, 256>>>(a2p, a2h, a2l);

    scal_reset_kernel<<<1,1>>>();
    pinv_sums_kernel<<<BHN, 256>>>();
    zinit_kernel<<<4096, 256>>>();

    __nv_bfloat16 *zch=z0h, *zcl=z0l, *zah=z1h, *zal=z1l;
    float *zcf=z0, *zaf=z1;
    for(int it=0; it<6; it++){
        // xz = +a2 @ z   (sign fixed: old mm256 alpha=-1,cdiag=0 double-negated)
        bmm256<<<dim3(4,2,BHN),128>>>(a2h, a2l, zch, zcl, 0.f, 1.f, xzh, xzl, nullptr);
        bmm256<<<dim3(4,2,BHN),128>>>(xzh, xzl, xzh, xzl, 7.f, -1.f, t1h, t1l, nullptr);
        bmm256<<<dim3(4,2,BHN),128>>>(xzh, xzl, t1h, t1l, 15.f, -1.f, t2h, t2l, nullptr);
        bmm256<<<dim3(4,2,BHN),128>>>(zch, zcl, t2h, t2l, 3.25f, -0.25f, zah, zal, zaf);
        __nv_bfloat16* th=zch; zch=zah; zah=th;
        __nv_bfloat16* tl=zcl; zcl=zal; zal=tl;
        float* tf=zcf; zcf=zaf; zaf=tf;
    }
    // zcf == z0 after 6 swaps; z2_kernel reads g_z0

    sim_kernel<<<dim3(64,2,BHN), 256>>>(qlp, kp, sim3p,
        (size_t)ML*DH, (size_t)NTOK*DH, (size_t)ML*NTOK, NTOK);
    softmax3_kernel<<<BHN*ML, 256>>>();
    a3v_kernel<<<dim3(8,2,BHN), 256>>>();
    a3v_reduce_kernel<<<1024, 256>>>();
    z2_kernel<<<dim3(2,BHN), 256>>>();
    conv_kernel<<<32768, 256>>>(cw);

    sim_kernel<<<dim3(2,64,BHN), 256>>>(qp, klp, sim3p,
        (size_t)NTOK*DH, (size_t)ML*DH, (size_t)NTOK*ML, ML);
    softmax256_kernel<<<BHN*NTOK/8, 256>>>(sim3p, nullptr, nullptr);
    a1z2_kernel<<<dim3(64,BHN), 256>>>();

    a2bf_kernel<<<8192, 256>>>();
    bf_gemm<<<dim3(4,128), 128, 65536>>>(bhi, blo, wohi, wolo, 1, x, bout, out);
}